// round 2
// baseline (speedup 1.0000x reference)
#include <cuda_runtime.h>
#include <cuda_bf16.h>

#define N_MAX 50000
#define E_MAX 800000
#define LRELU 0.2f
#define ENC_NEGINF 0x007FFFFFu

// ---------------- device scratch (no allocations allowed) ----------------
__device__ float g_h[N_MAX * 256];     // per-layer h = x@W
__device__ float g_x1[N_MAX * 256];    // layer outputs (x1, then final h)
__device__ float g_als[N_MAX * 4];
__device__ float g_ald[N_MAX * 4];
__device__ float g_p[E_MAX * 4];       // exp(leakyrelu(alpha)) per edge per head
__device__ int   g_deg[N_MAX];
__device__ int   g_offs[N_MAX];
__device__ int   g_cursor[N_MAX];
__device__ int   g_elist[E_MAX];
__device__ int   g_bsum[64];
__device__ int   g_bsumScan[64];

__device__ float g_asEff0[5 * 4], g_adEff0[5 * 4], g_aeEff0[4 * 4], g_selfae0[4];
__device__ float g_asEff1[256 * 4], g_adEff1[256 * 4], g_aeEff1[4 * 4], g_selfae1[4];
__device__ float g_meanRaw[4];

__device__ float    g_meansum[256];
__device__ unsigned g_maxbits[256];
__device__ float    g_attsum[256];
__device__ float    g_s[N_MAX];
__device__ float    g_pn[N_MAX];
__device__ unsigned g_smaxbits;
__device__ float    g_Z;

// ---------------- helpers ----------------
__device__ __forceinline__ unsigned encf(float f) {
    unsigned b = __float_as_uint(f);
    return (b & 0x80000000u) ? ~b : (b | 0x80000000u);
}
__device__ __forceinline__ float decf(unsigned u) {
    return (u & 0x80000000u) ? __uint_as_float(u ^ 0x80000000u) : __uint_as_float(~u);
}
__device__ __forceinline__ float lrelu(float a) { return a > 0.f ? a : LRELU * a; }

// ---------------- kernels ----------------
__global__ void k_zero(int N) {
    int i = blockIdx.x * blockDim.x + threadIdx.x;
    if (i < N) { g_deg[i] = 0; g_cursor[i] = 0; }
    if (i < 256) { g_meansum[i] = 0.f; g_attsum[i] = 0.f; g_maxbits[i] = ENC_NEGINF; }
    if (i < 4) g_meanRaw[i] = 0.f;
    if (i == 0) { g_Z = 0.f; g_smaxbits = ENC_NEGINF; }
}

__global__ void k_meanEA(const float* __restrict__ ea, int E) {
    __shared__ float sm[256][4];
    float a0 = 0, a1 = 0, a2 = 0, a3 = 0;
    int stride = gridDim.x * blockDim.x;
    for (int e = blockIdx.x * blockDim.x + threadIdx.x; e < E; e += stride) {
        float4 v = ((const float4*)ea)[e];
        a0 += v.x; a1 += v.y; a2 += v.z; a3 += v.w;
    }
    sm[threadIdx.x][0] = a0; sm[threadIdx.x][1] = a1;
    sm[threadIdx.x][2] = a2; sm[threadIdx.x][3] = a3;
    __syncthreads();
    for (int s = 128; s > 0; s >>= 1) {
        if (threadIdx.x < s) {
            sm[threadIdx.x][0] += sm[threadIdx.x + s][0];
            sm[threadIdx.x][1] += sm[threadIdx.x + s][1];
            sm[threadIdx.x][2] += sm[threadIdx.x + s][2];
            sm[threadIdx.x][3] += sm[threadIdx.x + s][3];
        }
        __syncthreads();
    }
    if (threadIdx.x < 4) atomicAdd(&g_meanRaw[threadIdx.x], sm[0][threadIdx.x]);
}

__global__ void k_deg(const int* __restrict__ dst, int E) {
    int e = blockIdx.x * blockDim.x + threadIdx.x;
    if (e < E) atomicAdd(&g_deg[dst[e]], 1);
}

__global__ void k_scanA(int N) {
    __shared__ int sm[1024];
    int i = blockIdx.x * 1024 + threadIdx.x;
    int v = (i < N) ? g_deg[i] : 0;
    sm[threadIdx.x] = v;
    __syncthreads();
    for (int d = 1; d < 1024; d <<= 1) {
        int t = (threadIdx.x >= d) ? sm[threadIdx.x - d] : 0;
        __syncthreads();
        sm[threadIdx.x] += t;
        __syncthreads();
    }
    if (i < N) g_offs[i] = sm[threadIdx.x] - v;  // exclusive
    if (threadIdx.x == 1023) g_bsum[blockIdx.x] = sm[1023];
}

__global__ void k_scanB(int NB) {
    __shared__ int sm[64];
    int t = threadIdx.x;
    int orig = (t < NB) ? g_bsum[t] : 0;
    sm[t] = orig;
    __syncthreads();
    for (int d = 1; d < 64; d <<= 1) {
        int v = (t >= d) ? sm[t - d] : 0;
        __syncthreads();
        sm[t] += v;
        __syncthreads();
    }
    g_bsumScan[t] = sm[t] - orig;  // exclusive
}

__global__ void k_scanC(int N) {
    int i = blockIdx.x * 1024 + threadIdx.x;
    if (i < N) g_offs[i] += g_bsumScan[blockIdx.x];
}

__global__ void k_place(const int* __restrict__ dst, int E) {
    int e = blockIdx.x * blockDim.x + threadIdx.x;
    if (e < E) {
        int d = dst[e];
        int pos = g_offs[d] + atomicAdd(&g_cursor[d], 1);
        g_elist[pos] = e;
    }
}

__global__ void k_pre(const float* __restrict__ W0, const float* __restrict__ as0,
                      const float* __restrict__ ad0, const float* __restrict__ We0,
                      const float* __restrict__ ae0, const float* __restrict__ W1,
                      const float* __restrict__ as1, const float* __restrict__ ad1,
                      const float* __restrict__ We1, const float* __restrict__ ae1,
                      float Ef) {
    __shared__ float sm_mean[4];
    int tid = threadIdx.x;
    for (int idx = tid; idx < 20; idx += 256) {
        int k = idx >> 2, h = idx & 3;
        float s1 = 0, s2 = 0;
        for (int c = 0; c < 64; c++) {
            float av = as0[h * 64 + c], dv = ad0[h * 64 + c];
            float w = W0[k * 256 + h * 64 + c];
            s1 += w * av; s2 += w * dv;
        }
        g_asEff0[idx] = s1; g_adEff0[idx] = s2;
    }
    for (int idx = tid; idx < 16; idx += 256) {
        int k = idx >> 2, h = idx & 3;
        float s0 = 0, s1 = 0;
        for (int c = 0; c < 64; c++) {
            s0 += We0[k * 256 + h * 64 + c] * ae0[h * 64 + c];
            s1 += We1[k * 256 + h * 64 + c] * ae1[h * 64 + c];
        }
        g_aeEff0[idx] = s0; g_aeEff1[idx] = s1;
    }
    for (int idx = tid; idx < 1024; idx += 256) {
        int k = idx >> 2, h = idx & 3;
        float s1 = 0, s2 = 0;
        for (int c = 0; c < 64; c++) {
            float w = W1[k * 256 + h * 64 + c];
            s1 += w * as1[h * 64 + c]; s2 += w * ad1[h * 64 + c];
        }
        g_asEff1[idx] = s1; g_adEff1[idx] = s2;
    }
    __syncthreads();
    if (tid < 4) sm_mean[tid] = g_meanRaw[tid] / Ef;
    __syncthreads();
    if (tid < 4) {
        float s0 = 0, s1 = 0;
        for (int k = 0; k < 4; k++) {
            s0 += sm_mean[k] * g_aeEff0[k * 4 + tid];
            s1 += sm_mean[k] * g_aeEff1[k * 4 + tid];
        }
        g_selfae0[tid] = s0; g_selfae1[tid] = s1;
    }
}

// layer 0 node kernel: h0 = x@W0, als0/ald0 via effective 5x4 matrices
__global__ void k_node0(const float* __restrict__ x, const float* __restrict__ W0, int N) {
    int n = blockIdx.x;
    if (n >= N) return;
    int tid = threadIdx.x;
    float xk[5];
#pragma unroll
    for (int k = 0; k < 5; k++) xk[k] = x[n * 5 + k];
    float s = 0.f;
#pragma unroll
    for (int k = 0; k < 5; k++) s += xk[k] * W0[k * 256 + tid];
    g_h[n * 256 + tid] = s;
    if (tid < 8) {
        int which = tid >> 2, h = tid & 3;
        const float* eff = which ? g_adEff0 : g_asEff0;
        float a = 0.f;
#pragma unroll
        for (int k = 0; k < 5; k++) a += xk[k] * eff[k * 4 + h];
        (which ? g_ald : g_als)[n * 4 + h] = a;
    }
}

// per-edge unnormalized attention weights p = exp(lrelu(als[s]+ald[d]+ale))
template <int L>
__global__ void k_edge(const int* __restrict__ src, const int* __restrict__ dst,
                       const float* __restrict__ ea, int E) {
    int e = blockIdx.x * blockDim.x + threadIdx.x;
    if (e >= E) return;
    const float* aeEff = L ? g_aeEff1 : g_aeEff0;
    float4 v = ((const float4*)ea)[e];
    int s = src[e], d = dst[e];
    float4 as = ((const float4*)g_als)[s];
    float4 ad = ((const float4*)g_ald)[d];
    float4 p;
    {
        float ale = v.x * aeEff[0] + v.y * aeEff[4] + v.z * aeEff[8] + v.w * aeEff[12];
        p.x = __expf(lrelu(as.x + ad.x + ale));
        ale = v.x * aeEff[1] + v.y * aeEff[5] + v.z * aeEff[9] + v.w * aeEff[13];
        p.y = __expf(lrelu(as.y + ad.y + ale));
        ale = v.x * aeEff[2] + v.y * aeEff[6] + v.z * aeEff[10] + v.w * aeEff[14];
        p.z = __expf(lrelu(as.z + ad.z + ale));
        ale = v.x * aeEff[3] + v.y * aeEff[7] + v.z * aeEff[11] + v.w * aeEff[15];
        p.w = __expf(lrelu(as.w + ad.w + ale));
    }
    ((float4*)g_p)[e] = p;
}

// warp per (node, head) gather: out = (p_self*h_self + sum p*h_src) / (denom)
template <int L>
__global__ void k_gather(const int* __restrict__ src, const float* __restrict__ b, int N) {
    int gw = (blockIdx.x * blockDim.x + threadIdx.x) >> 5;
    int lane = threadIdx.x & 31;
    int n = gw >> 2, h = gw & 3;
    if (n >= N) return;
    const float* selfae = L ? g_selfae1 : g_selfae0;
    float als = g_als[n * 4 + h], ald = g_ald[n * 4 + h];
    float pself = __expf(lrelu(als + ald + selfae[h]));
    const float* hrow = g_h + (size_t)n * 256 + h * 64;
    float acc0 = pself * hrow[lane];
    float acc1 = pself * hrow[lane + 32];
    float denom = pself;
    int base = g_offs[n], deg = g_deg[n];
    int i = 0;
    int e_next = (deg > 0) ? g_elist[base] : 0;
    for (i = 0; i < deg; i++) {
        int e = e_next;
        if (i + 1 < deg) e_next = g_elist[base + i + 1];
        int s = src[e];
        float pv = g_p[e * 4 + h];
        const float* hs = g_h + (size_t)s * 256 + h * 64;
        acc0 += pv * hs[lane];
        acc1 += pv * hs[lane + 32];
        denom += pv;
    }
    float inv = 1.f / (denom + 1e-16f);
    int c0 = h * 64 + lane;
    float o0 = acc0 * inv + b[c0];
    float o1 = acc1 * inv + b[c0 + 32];
    if (L == 0) { o0 = fmaxf(o0, 0.f); o1 = fmaxf(o1, 0.f); }
    g_x1[(size_t)n * 256 + c0] = o0;
    g_x1[(size_t)n * 256 + c0 + 32] = o1;
}

// layer 1: h1 = x1@W1 (16 nodes per block), plus als1/ald1
__global__ __launch_bounds__(256) void k_node1(const float* __restrict__ W1, int N) {
    __shared__ float xs[16 * 256];
    int tid = threadIdx.x;
    int n0 = blockIdx.x * 16;
    for (int j = 0; j < 16; j++) {
        int n = n0 + j;
        xs[j * 256 + tid] = (n < N) ? g_x1[(size_t)n * 256 + tid] : 0.f;
    }
    __syncthreads();
    float acc[16];
#pragma unroll
    for (int j = 0; j < 16; j++) acc[j] = 0.f;
#pragma unroll 4
    for (int k = 0; k < 256; k++) {
        float w = W1[k * 256 + tid];
#pragma unroll
        for (int j = 0; j < 16; j++) acc[j] += xs[j * 256 + k] * w;
    }
    for (int j = 0; j < 16; j++) {
        int n = n0 + j;
        if (n < N) g_h[(size_t)n * 256 + tid] = acc[j];
    }
    // attention logits: 16 nodes x 4 heads x {src,dst}
    if (tid < 128) {
        int which = tid >> 6;
        int t2 = tid & 63;
        int j = t2 >> 2, h = t2 & 3;
        const float* eff = which ? g_adEff1 : g_asEff1;
        float s = 0.f;
        for (int k = 0; k < 256; k++) s += xs[j * 256 + k] * eff[k * 4 + h];
        int n = n0 + j;
        if (n < N) (which ? g_ald : g_als)[n * 4 + h] = s;
    }
}

// mean + max pooling partials (block handles 64 nodes, thread = channel)
__global__ void k_pool1(int N) {
    int c = threadIdx.x;
    int nb = blockIdx.x * 64;
    float s = 0.f, mx = -3.402823466e38f;
    for (int j = 0; j < 64; j++) {
        int n = nb + j;
        if (n < N) {
            float v = g_x1[(size_t)n * 256 + c];
            s += v;
            mx = fmaxf(mx, v);
        }
    }
    atomicAdd(&g_meansum[c], s);
    atomicMax(&g_maxbits[c], encf(mx));
}

__global__ void k_fin(int N) {
    int c = threadIdx.x;
    g_meansum[c] /= (float)N;  // now holds the mean
}

// s[n] = h[n] . mean ; track global max
__global__ void k_dot(int N) {
    int gw = (blockIdx.x * blockDim.x + threadIdx.x) >> 5;
    int lane = threadIdx.x & 31;
    if (gw >= N) return;
    float s = 0.f;
#pragma unroll
    for (int i = 0; i < 8; i++) {
        int c = lane + i * 32;
        s += g_x1[(size_t)gw * 256 + c] * g_meansum[c];
    }
#pragma unroll
    for (int o = 16; o > 0; o >>= 1) s += __shfl_down_sync(0xFFFFFFFFu, s, o);
    if (lane == 0) {
        g_s[gw] = s;
        atomicMax(&g_smaxbits, encf(s));
    }
}

__global__ void k_exp(int N) {
    __shared__ float sm[256];
    int i = blockIdx.x * blockDim.x + threadIdx.x;
    float smax = decf(g_smaxbits);
    float v = 0.f;
    if (i < N) {
        v = __expf(g_s[i] - smax);
        g_pn[i] = v;
    }
    sm[threadIdx.x] = v;
    __syncthreads();
    for (int s = 128; s > 0; s >>= 1) {
        if (threadIdx.x < s) sm[threadIdx.x] += sm[threadIdx.x + s];
        __syncthreads();
    }
    if (threadIdx.x == 0) atomicAdd(&g_Z, sm[0]);
}

__global__ void k_attpool(int N) {
    int c = threadIdx.x;
    int nb = blockIdx.x * 64;
    float s = 0.f;
    for (int j = 0; j < 64; j++) {
        int n = nb + j;
        if (n < N) s += g_x1[(size_t)n * 256 + c] * g_pn[n];
    }
    atomicAdd(&g_attsum[c], s);
}

__global__ void k_mlp(const float* __restrict__ Wm1, const float* __restrict__ bm1,
                      const float* __restrict__ Wm2, const float* __restrict__ bm2,
                      const float* __restrict__ Wm3, const float* __restrict__ bm3,
                      float* __restrict__ out) {
    __shared__ float comb[768], z1[128], z2[64];
    int tid = threadIdx.x;
    float Zinv = 1.f / g_Z;
    comb[tid] = g_meansum[tid];
    comb[256 + tid] = decf(g_maxbits[tid]);
    comb[512 + tid] = g_attsum[tid] * Zinv;
    __syncthreads();
    if (tid < 128) {
        float s = bm1[tid];
        for (int k = 0; k < 768; k++) s += comb[k] * Wm1[k * 128 + tid];
        z1[tid] = fmaxf(s, 0.f);
    }
    __syncthreads();
    if (tid < 64) {
        float s = bm2[tid];
        for (int k = 0; k < 128; k++) s += z1[k] * Wm2[k * 64 + tid];
        z2[tid] = fmaxf(s, 0.f);
    }
    __syncthreads();
    if (tid < 128) {
        float s = bm3[tid];
        for (int k = 0; k < 64; k++) s += z2[k] * Wm3[k * 128 + tid];
        out[tid] = s;
    }
}

// ---------------- launch ----------------
extern "C" void kernel_launch(void* const* d_in, const int* in_sizes, int n_in,
                              void* d_out, int out_size) {
    const float* x   = (const float*)d_in[0];
    const int*   ei  = (const int*)d_in[1];
    const float* ea  = (const float*)d_in[2];
    const float* W0  = (const float*)d_in[3];
    const float* as0 = (const float*)d_in[4];
    const float* ad0 = (const float*)d_in[5];
    const float* We0 = (const float*)d_in[6];
    const float* ae0 = (const float*)d_in[7];
    const float* b0  = (const float*)d_in[8];
    const float* W1  = (const float*)d_in[9];
    const float* as1 = (const float*)d_in[10];
    const float* ad1 = (const float*)d_in[11];
    const float* We1 = (const float*)d_in[12];
    const float* ae1 = (const float*)d_in[13];
    const float* b1  = (const float*)d_in[14];
    const float* Wm1 = (const float*)d_in[15];
    const float* bm1 = (const float*)d_in[16];
    const float* Wm2 = (const float*)d_in[17];
    const float* bm2 = (const float*)d_in[18];
    const float* Wm3 = (const float*)d_in[19];
    const float* bm3 = (const float*)d_in[20];

    int N = in_sizes[0] / 5;
    int E = in_sizes[1] / 2;
    const int* src = ei;
    const int* dst = ei + E;

    int NB = (N + 1023) / 1024;
    int EB = (E + 255) / 256;

    k_zero<<<(N + 255) / 256, 256>>>(N);
    k_meanEA<<<512, 256>>>(ea, E);
    k_deg<<<EB, 256>>>(dst, E);
    k_scanA<<<NB, 1024>>>(N);
    k_scanB<<<1, 64>>>(NB);
    k_scanC<<<NB, 1024>>>(N);
    k_place<<<EB, 256>>>(dst, E);
    k_pre<<<1, 256>>>(W0, as0, ad0, We0, ae0, W1, as1, ad1, We1, ae1, (float)E);

    // layer 0
    k_node0<<<N, 256>>>(x, W0, N);
    k_edge<0><<<EB, 256>>>(src, dst, ea, E);
    {
        long long warps = (long long)N * 4;
        int blocks = (int)((warps * 32 + 255) / 256);
        k_gather<0><<<blocks, 256>>>(src, b0, N);
    }
    // layer 1
    k_node1<<<(N + 15) / 16, 256>>>(W1, N);
    k_edge<1><<<EB, 256>>>(src, dst, ea, E);
    {
        long long warps = (long long)N * 4;
        int blocks = (int)((warps * 32 + 255) / 256);
        k_gather<1><<<blocks, 256>>>(src, b1, N);
    }
    // pooling + MLP
    k_pool1<<<(N + 63) / 64, 256>>>(N);
    k_fin<<<1, 256>>>(N);
    k_dot<<<(N * 32 + 255) / 256, 256>>>(N);
    k_exp<<<(N + 255) / 256, 256>>>(N);
    k_attpool<<<(N + 63) / 64, 256>>>(N);
    k_mlp<<<1, 256>>>(Wm1, bm1, Wm2, bm2, Wm3, bm3, (float*)d_out);
}

// round 3
// speedup vs baseline: 1.4331x; 1.4331x over previous
#include <cuda_runtime.h>
#include <cuda_bf16.h>
#include <cfloat>

#define N_MAX 50000
#define E_MAX 800000
#define PB_MAX ((N_MAX + 7) / 8)
#define LRELU 0.2f
#define ENC_NEGINF 0x007FFFFFu

// ---------------- device scratch ----------------
__device__ float g_h[N_MAX * 256];
__device__ float g_x1[N_MAX * 256];
__device__ float g_als[N_MAX * 4];
__device__ float g_ald[N_MAX * 4];
__device__ float g_p[E_MAX * 4];       // permuted (CSR order): g_p[pos*4+h]
__device__ int   g_deg[N_MAX];
__device__ int   g_offs[N_MAX];
__device__ int   g_cursor[N_MAX];
__device__ int   g_srcPerm[E_MAX];     // src node id in CSR position order
__device__ int   g_epos[E_MAX];        // edge -> CSR position
__device__ int   g_bsum[64];
__device__ int   g_bsumScan[64];
__device__ float g_poolSum[PB_MAX * 256];
__device__ float g_poolMax[PB_MAX * 256];

__device__ float g_asEff0[5 * 4], g_adEff0[5 * 4], g_aeEff0[4 * 4], g_selfae0[4];
__device__ float g_asEff1[256 * 4], g_adEff1[256 * 4], g_aeEff1[4 * 4], g_selfae1[4];
__device__ float g_meanRaw[4];

__device__ float    g_meansum[256];
__device__ unsigned g_maxbits[256];
__device__ float    g_attsum[256];
__device__ float    g_s[N_MAX];
__device__ float    g_pn[N_MAX];
__device__ unsigned g_smaxbits;
__device__ float    g_Z;

// ---------------- helpers ----------------
__device__ __forceinline__ unsigned encf(float f) {
    unsigned b = __float_as_uint(f);
    return (b & 0x80000000u) ? ~b : (b | 0x80000000u);
}
__device__ __forceinline__ float decf(unsigned u) {
    return (u & 0x80000000u) ? __uint_as_float(u ^ 0x80000000u) : __uint_as_float(~u);
}
__device__ __forceinline__ float lrelu(float a) { return a > 0.f ? a : LRELU * a; }

__device__ __forceinline__ unsigned long long packf2(float lo, float hi) {
    unsigned long long r;
    unsigned a = __float_as_uint(lo), b = __float_as_uint(hi);
    asm("mov.b64 %0, {%1, %2};" : "=l"(r) : "r"(a), "r"(b));
    return r;
}
__device__ __forceinline__ float unpack_sum(unsigned long long v) {
    unsigned a, b;
    asm("mov.b64 {%0, %1}, %2;" : "=r"(a), "=r"(b) : "l"(v));
    return __uint_as_float(a) + __uint_as_float(b);
}
__device__ __forceinline__ void ffma2(unsigned long long& acc, unsigned long long a,
                                      unsigned long long b) {
    asm("fma.rn.f32x2 %0, %1, %2, %0;" : "+l"(acc) : "l"(a), "l"(b));
}

// ---------------- setup kernels ----------------
__global__ void k_zero(int N) {
    int i = blockIdx.x * blockDim.x + threadIdx.x;
    if (i < N) { g_deg[i] = 0; g_cursor[i] = 0; }
    if (i < 256) { g_meansum[i] = 0.f; g_attsum[i] = 0.f; g_maxbits[i] = ENC_NEGINF; }
    if (i < 4) g_meanRaw[i] = 0.f;
    if (i == 0) { g_Z = 0.f; g_smaxbits = ENC_NEGINF; }
}

__global__ void k_meanEA(const float* __restrict__ ea, int E) {
    __shared__ float sm[256][4];
    float a0 = 0, a1 = 0, a2 = 0, a3 = 0;
    int stride = gridDim.x * blockDim.x;
    for (int e = blockIdx.x * blockDim.x + threadIdx.x; e < E; e += stride) {
        float4 v = ((const float4*)ea)[e];
        a0 += v.x; a1 += v.y; a2 += v.z; a3 += v.w;
    }
    sm[threadIdx.x][0] = a0; sm[threadIdx.x][1] = a1;
    sm[threadIdx.x][2] = a2; sm[threadIdx.x][3] = a3;
    __syncthreads();
    for (int s = 128; s > 0; s >>= 1) {
        if (threadIdx.x < s) {
            sm[threadIdx.x][0] += sm[threadIdx.x + s][0];
            sm[threadIdx.x][1] += sm[threadIdx.x + s][1];
            sm[threadIdx.x][2] += sm[threadIdx.x + s][2];
            sm[threadIdx.x][3] += sm[threadIdx.x + s][3];
        }
        __syncthreads();
    }
    if (threadIdx.x < 4) atomicAdd(&g_meanRaw[threadIdx.x], sm[0][threadIdx.x]);
}

__global__ void k_deg(const int* __restrict__ dst, int E) {
    int e = blockIdx.x * blockDim.x + threadIdx.x;
    if (e < E) atomicAdd(&g_deg[dst[e]], 1);
}

__global__ void k_scanA(int N) {
    __shared__ int sm[1024];
    int i = blockIdx.x * 1024 + threadIdx.x;
    int v = (i < N) ? g_deg[i] : 0;
    sm[threadIdx.x] = v;
    __syncthreads();
    for (int d = 1; d < 1024; d <<= 1) {
        int t = (threadIdx.x >= d) ? sm[threadIdx.x - d] : 0;
        __syncthreads();
        sm[threadIdx.x] += t;
        __syncthreads();
    }
    if (i < N) g_offs[i] = sm[threadIdx.x] - v;
    if (threadIdx.x == 1023) g_bsum[blockIdx.x] = sm[1023];
}

__global__ void k_scanB(int NB) {
    __shared__ int sm[64];
    int t = threadIdx.x;
    int orig = (t < NB) ? g_bsum[t] : 0;
    sm[t] = orig;
    __syncthreads();
    for (int d = 1; d < 64; d <<= 1) {
        int v = (t >= d) ? sm[t - d] : 0;
        __syncthreads();
        sm[t] += v;
        __syncthreads();
    }
    g_bsumScan[t] = sm[t] - orig;
}

__global__ void k_scanC(int N) {
    int i = blockIdx.x * 1024 + threadIdx.x;
    if (i < N) g_offs[i] += g_bsumScan[blockIdx.x];
}

__global__ void k_place(const int* __restrict__ src, const int* __restrict__ dst, int E) {
    int e = blockIdx.x * blockDim.x + threadIdx.x;
    if (e < E) {
        int d = dst[e];
        int pos = g_offs[d] + atomicAdd(&g_cursor[d], 1);
        g_epos[e] = pos;
        g_srcPerm[pos] = src[e];
    }
}

__global__ void k_pre(const float* __restrict__ W0, const float* __restrict__ as0,
                      const float* __restrict__ ad0, const float* __restrict__ We0,
                      const float* __restrict__ ae0, const float* __restrict__ W1,
                      const float* __restrict__ as1, const float* __restrict__ ad1,
                      const float* __restrict__ We1, const float* __restrict__ ae1,
                      float Ef) {
    __shared__ float sm_mean[4];
    int tid = threadIdx.x;
    for (int idx = tid; idx < 20; idx += 256) {
        int k = idx >> 2, h = idx & 3;
        float s1 = 0, s2 = 0;
        for (int c = 0; c < 64; c++) {
            float w = W0[k * 256 + h * 64 + c];
            s1 += w * as0[h * 64 + c]; s2 += w * ad0[h * 64 + c];
        }
        g_asEff0[idx] = s1; g_adEff0[idx] = s2;
    }
    for (int idx = tid; idx < 16; idx += 256) {
        int k = idx >> 2, h = idx & 3;
        float s0 = 0, s1 = 0;
        for (int c = 0; c < 64; c++) {
            s0 += We0[k * 256 + h * 64 + c] * ae0[h * 64 + c];
            s1 += We1[k * 256 + h * 64 + c] * ae1[h * 64 + c];
        }
        g_aeEff0[idx] = s0; g_aeEff1[idx] = s1;
    }
    for (int idx = tid; idx < 1024; idx += 256) {
        int k = idx >> 2, h = idx & 3;
        float s1 = 0, s2 = 0;
        for (int c = 0; c < 64; c++) {
            float w = W1[k * 256 + h * 64 + c];
            s1 += w * as1[h * 64 + c]; s2 += w * ad1[h * 64 + c];
        }
        g_asEff1[idx] = s1; g_adEff1[idx] = s2;
    }
    __syncthreads();
    if (tid < 4) sm_mean[tid] = g_meanRaw[tid] / Ef;
    __syncthreads();
    if (tid < 4) {
        float s0 = 0, s1 = 0;
        for (int k = 0; k < 4; k++) {
            s0 += sm_mean[k] * g_aeEff0[k * 4 + tid];
            s1 += sm_mean[k] * g_aeEff1[k * 4 + tid];
        }
        g_selfae0[tid] = s0; g_selfae1[tid] = s1;
    }
}

// ---------------- layer 0 node transform ----------------
__global__ void k_node0(const float* __restrict__ x, const float* __restrict__ W0, int N) {
    int n = blockIdx.x;
    if (n >= N) return;
    int tid = threadIdx.x;
    float xk[5];
#pragma unroll
    for (int k = 0; k < 5; k++) xk[k] = x[n * 5 + k];
    float s = 0.f;
#pragma unroll
    for (int k = 0; k < 5; k++) s += xk[k] * W0[k * 256 + tid];
    g_h[(size_t)n * 256 + tid] = s;
    if (tid < 8) {
        int which = tid >> 2, h = tid & 3;
        const float* eff = which ? g_adEff0 : g_asEff0;
        float a = 0.f;
#pragma unroll
        for (int k = 0; k < 5; k++) a += xk[k] * eff[k * 4 + h];
        (which ? g_ald : g_als)[n * 4 + h] = a;
    }
}

// ---------------- per-edge attention weights (written in CSR order) ----------------
template <int L>
__global__ void k_edge(const int* __restrict__ src, const int* __restrict__ dst,
                       const float* __restrict__ ea, int E) {
    int e = blockIdx.x * blockDim.x + threadIdx.x;
    if (e >= E) return;
    const float* aeEff = L ? g_aeEff1 : g_aeEff0;
    float4 v = ((const float4*)ea)[e];
    int s = src[e], d = dst[e];
    float4 as = ((const float4*)g_als)[s];
    float4 ad = ((const float4*)g_ald)[d];
    float4 p;
    float ale;
    ale = v.x * aeEff[0] + v.y * aeEff[4] + v.z * aeEff[8] + v.w * aeEff[12];
    p.x = __expf(lrelu(as.x + ad.x + ale));
    ale = v.x * aeEff[1] + v.y * aeEff[5] + v.z * aeEff[9] + v.w * aeEff[13];
    p.y = __expf(lrelu(as.y + ad.y + ale));
    ale = v.x * aeEff[2] + v.y * aeEff[6] + v.z * aeEff[10] + v.w * aeEff[14];
    p.z = __expf(lrelu(as.z + ad.z + ale));
    ale = v.x * aeEff[3] + v.y * aeEff[7] + v.z * aeEff[11] + v.w * aeEff[15];
    p.w = __expf(lrelu(as.w + ad.w + ale));
    ((float4*)g_p)[g_epos[e]] = p;
}

// ---------------- gather: one warp per node, all 4 heads ----------------
// lane owns channels [lane*8, lane*8+8); head = lane>>3
template <int L>
__global__ __launch_bounds__(256) void k_gather(const float* __restrict__ b, int N) {
    int wib = threadIdx.x >> 5;
    int lane = threadIdx.x & 31;
    int n = blockIdx.x * 8 + wib;
    int hh = lane >> 3;
    bool active = (n < N);
    float o0 = 0, o1 = 0, o2 = 0, o3 = 0, o4 = 0, o5 = 0, o6 = 0, o7 = 0;
    if (active) {
        const float* selfae = L ? g_selfae1 : g_selfae0;
        float pself = __expf(lrelu(g_als[n * 4 + hh] + g_ald[n * 4 + hh] + selfae[hh]));
        const float4* hp = (const float4*)(g_h + (size_t)n * 256) + lane * 2;
        float4 v0 = hp[0], v1 = hp[1];
        float a0 = pself * v0.x, a1 = pself * v0.y, a2 = pself * v0.z, a3 = pself * v0.w;
        float a4 = pself * v1.x, a5 = pself * v1.y, a6 = pself * v1.z, a7 = pself * v1.w;
        float denom = pself;
        int base = g_offs[n], deg = g_deg[n];
        for (int i0 = 0; i0 < deg; i0 += 32) {
            int cnt = min(32, deg - i0);
            int sl = 0;
            if (lane < cnt) sl = g_srcPerm[base + i0 + lane];
            int j = 0;
            for (; j + 4 <= cnt; j += 4) {
                int s0 = __shfl_sync(0xFFFFFFFFu, sl, j);
                int s1 = __shfl_sync(0xFFFFFFFFu, sl, j + 1);
                int s2 = __shfl_sync(0xFFFFFFFFu, sl, j + 2);
                int s3 = __shfl_sync(0xFFFFFFFFu, sl, j + 3);
                size_t pb = (size_t)(base + i0 + j) * 4 + hh;
                float p0 = g_p[pb], p1 = g_p[pb + 4], p2 = g_p[pb + 8], p3 = g_p[pb + 12];
                const float4* q0 = (const float4*)(g_h + (size_t)s0 * 256) + lane * 2;
                const float4* q1 = (const float4*)(g_h + (size_t)s1 * 256) + lane * 2;
                const float4* q2 = (const float4*)(g_h + (size_t)s2 * 256) + lane * 2;
                const float4* q3 = (const float4*)(g_h + (size_t)s3 * 256) + lane * 2;
                float4 u00 = q0[0], u01 = q0[1];
                float4 u10 = q1[0], u11 = q1[1];
                float4 u20 = q2[0], u21 = q2[1];
                float4 u30 = q3[0], u31 = q3[1];
                a0 += p0 * u00.x; a1 += p0 * u00.y; a2 += p0 * u00.z; a3 += p0 * u00.w;
                a4 += p0 * u01.x; a5 += p0 * u01.y; a6 += p0 * u01.z; a7 += p0 * u01.w;
                a0 += p1 * u10.x; a1 += p1 * u10.y; a2 += p1 * u10.z; a3 += p1 * u10.w;
                a4 += p1 * u11.x; a5 += p1 * u11.y; a6 += p1 * u11.z; a7 += p1 * u11.w;
                a0 += p2 * u20.x; a1 += p2 * u20.y; a2 += p2 * u20.z; a3 += p2 * u20.w;
                a4 += p2 * u21.x; a5 += p2 * u21.y; a6 += p2 * u21.z; a7 += p2 * u21.w;
                a0 += p3 * u30.x; a1 += p3 * u30.y; a2 += p3 * u30.z; a3 += p3 * u30.w;
                a4 += p3 * u31.x; a5 += p3 * u31.y; a6 += p3 * u31.z; a7 += p3 * u31.w;
                denom += p0 + p1 + p2 + p3;
            }
            for (; j < cnt; j++) {
                int s0 = __shfl_sync(0xFFFFFFFFu, sl, j);
                float p0 = g_p[(size_t)(base + i0 + j) * 4 + hh];
                const float4* q0 = (const float4*)(g_h + (size_t)s0 * 256) + lane * 2;
                float4 u00 = q0[0], u01 = q0[1];
                a0 += p0 * u00.x; a1 += p0 * u00.y; a2 += p0 * u00.z; a3 += p0 * u00.w;
                a4 += p0 * u01.x; a5 += p0 * u01.y; a6 += p0 * u01.z; a7 += p0 * u01.w;
                denom += p0;
            }
        }
        float inv = 1.f / (denom + 1e-16f);
        int c = lane * 8;
        o0 = a0 * inv + b[c + 0]; o1 = a1 * inv + b[c + 1];
        o2 = a2 * inv + b[c + 2]; o3 = a3 * inv + b[c + 3];
        o4 = a4 * inv + b[c + 4]; o5 = a5 * inv + b[c + 5];
        o6 = a6 * inv + b[c + 6]; o7 = a7 * inv + b[c + 7];
        if (L == 0) {
            o0 = fmaxf(o0, 0.f); o1 = fmaxf(o1, 0.f); o2 = fmaxf(o2, 0.f); o3 = fmaxf(o3, 0.f);
            o4 = fmaxf(o4, 0.f); o5 = fmaxf(o5, 0.f); o6 = fmaxf(o6, 0.f); o7 = fmaxf(o7, 0.f);
        }
        float* op = g_x1 + (size_t)n * 256 + c;
        ((float4*)op)[0] = make_float4(o0, o1, o2, o3);
        ((float4*)op)[1] = make_float4(o4, o5, o6, o7);
    }
    if (L == 1) {
        // fused mean/max pool partials: transpose through smem, per-block partial
        __shared__ float tile[8 * 256];
        if (active) {
            float* tp = tile + wib * 256 + lane * 8;
            ((float4*)tp)[0] = make_float4(o0, o1, o2, o3);
            ((float4*)tp)[1] = make_float4(o4, o5, o6, o7);
        }
        __syncthreads();
        int c = threadIdx.x;  // 0..255 = channel
        int nb = min(8, N - blockIdx.x * 8);
        float s = 0.f, m = -FLT_MAX;
        for (int w = 0; w < nb; w++) {
            float v = tile[w * 256 + c];
            s += v;
            m = fmaxf(m, v);
        }
        g_poolSum[(size_t)blockIdx.x * 256 + c] = s;
        g_poolMax[(size_t)blockIdx.x * 256 + c] = m;
    }
}

// ---------------- layer 1 node transform: 32 nodes/block, packed f32x2 FMA ----------------
__global__ __launch_bounds__(256) void k_node1(const float* __restrict__ W1, int N) {
    __shared__ __align__(16) float xs[32 * 256];
    int tid = threadIdx.x;
    int n0 = blockIdx.x * 32;
    for (int j = 0; j < 32; j++) {
        int n = n0 + j;
        xs[j * 256 + tid] = (n < N) ? g_x1[(size_t)n * 256 + tid] : 0.f;
    }
    __syncthreads();
    unsigned long long acc[32];
#pragma unroll
    for (int j = 0; j < 32; j++) acc[j] = 0ull;
    for (int k = 0; k < 256; k += 4) {
        float wa = W1[(k + 0) * 256 + tid];
        float wb = W1[(k + 1) * 256 + tid];
        float wc = W1[(k + 2) * 256 + tid];
        float wd = W1[(k + 3) * 256 + tid];
        unsigned long long w01 = packf2(wa, wb);
        unsigned long long w23 = packf2(wc, wd);
#pragma unroll
        for (int j = 0; j < 32; j++) {
            ulonglong2 x2 = *(const ulonglong2*)&xs[j * 256 + k];
            ffma2(acc[j], x2.x, w01);
            ffma2(acc[j], x2.y, w23);
        }
    }
    for (int j = 0; j < 32; j++) {
        int n = n0 + j;
        if (n < N) g_h[(size_t)n * 256 + tid] = unpack_sum(acc[j]);
    }
    // attention logits: 32 nodes x 4 heads x {src,dst} = 256 tasks
    {
        const float* eff = (tid & 128) ? g_adEff1 : g_asEff1;
        int t2 = tid & 127;
        int j = t2 >> 2, h = t2 & 3;
        float s = 0.f;
        for (int k = 0; k < 256; k += 4) {
            float4 xv = *(const float4*)&xs[j * 256 + k];
            s += xv.x * eff[(k + 0) * 4 + h] + xv.y * eff[(k + 1) * 4 + h] +
                 xv.z * eff[(k + 2) * 4 + h] + xv.w * eff[(k + 3) * 4 + h];
        }
        int n = n0 + j;
        if (n < N) ((tid & 128) ? g_ald : g_als)[n * 4 + h] = s;
    }
}

// ---------------- pooling finalize ----------------
__global__ void k_poolfin(int NB) {
    int c = threadIdx.x;
    float s = 0.f, m = -FLT_MAX;
    for (int i = blockIdx.x; i < NB; i += gridDim.x) {
        s += g_poolSum[(size_t)i * 256 + c];
        m = fmaxf(m, g_poolMax[(size_t)i * 256 + c]);
    }
    atomicAdd(&g_meansum[c], s);
    atomicMax(&g_maxbits[c], encf(m));
}

__global__ void k_fin(int N) {
    int c = threadIdx.x;
    g_meansum[c] /= (float)N;
}

__global__ void k_dot(int N) {
    int gw = (blockIdx.x * blockDim.x + threadIdx.x) >> 5;
    int lane = threadIdx.x & 31;
    if (gw >= N) return;
    float s = 0.f;
#pragma unroll
    for (int i = 0; i < 8; i++) {
        int c = lane + i * 32;
        s += g_x1[(size_t)gw * 256 + c] * g_meansum[c];
    }
#pragma unroll
    for (int o = 16; o > 0; o >>= 1) s += __shfl_down_sync(0xFFFFFFFFu, s, o);
    if (lane == 0) {
        g_s[gw] = s;
        atomicMax(&g_smaxbits, encf(s));
    }
}

__global__ void k_exp(int N) {
    __shared__ float sm[256];
    int i = blockIdx.x * blockDim.x + threadIdx.x;
    float smax = decf(g_smaxbits);
    float v = 0.f;
    if (i < N) {
        v = __expf(g_s[i] - smax);
        g_pn[i] = v;
    }
    sm[threadIdx.x] = v;
    __syncthreads();
    for (int s = 128; s > 0; s >>= 1) {
        if (threadIdx.x < s) sm[threadIdx.x] += sm[threadIdx.x + s];
        __syncthreads();
    }
    if (threadIdx.x == 0) atomicAdd(&g_Z, sm[0]);
}

__global__ void k_attpool(int N) {
    int c = threadIdx.x;
    int nb = blockIdx.x * 64;
    float s = 0.f;
    for (int j = 0; j < 64; j++) {
        int n = nb + j;
        if (n < N) s += g_x1[(size_t)n * 256 + c] * g_pn[n];
    }
    atomicAdd(&g_attsum[c], s);
}

__global__ void k_mlp(const float* __restrict__ Wm1, const float* __restrict__ bm1,
                      const float* __restrict__ Wm2, const float* __restrict__ bm2,
                      const float* __restrict__ Wm3, const float* __restrict__ bm3,
                      float* __restrict__ out) {
    __shared__ float comb[768], z1[128], z2[64];
    int tid = threadIdx.x;
    float Zinv = 1.f / g_Z;
    comb[tid] = g_meansum[tid];
    comb[256 + tid] = decf(g_maxbits[tid]);
    comb[512 + tid] = g_attsum[tid] * Zinv;
    __syncthreads();
    if (tid < 128) {
        float s = bm1[tid];
        for (int k = 0; k < 768; k++) s += comb[k] * Wm1[k * 128 + tid];
        z1[tid] = fmaxf(s, 0.f);
    }
    __syncthreads();
    if (tid < 64) {
        float s = bm2[tid];
        for (int k = 0; k < 128; k++) s += z1[k] * Wm2[k * 64 + tid];
        z2[tid] = fmaxf(s, 0.f);
    }
    __syncthreads();
    if (tid < 128) {
        float s = bm3[tid];
        for (int k = 0; k < 64; k++) s += z2[k] * Wm3[k * 128 + tid];
        out[tid] = s;
    }
}

// ---------------- launch ----------------
extern "C" void kernel_launch(void* const* d_in, const int* in_sizes, int n_in,
                              void* d_out, int out_size) {
    const float* x   = (const float*)d_in[0];
    const int*   ei  = (const int*)d_in[1];
    const float* ea  = (const float*)d_in[2];
    const float* W0  = (const float*)d_in[3];
    const float* as0 = (const float*)d_in[4];
    const float* ad0 = (const float*)d_in[5];
    const float* We0 = (const float*)d_in[6];
    const float* ae0 = (const float*)d_in[7];
    const float* b0  = (const float*)d_in[8];
    const float* W1  = (const float*)d_in[9];
    const float* as1 = (const float*)d_in[10];
    const float* ad1 = (const float*)d_in[11];
    const float* We1 = (const float*)d_in[12];
    const float* ae1 = (const float*)d_in[13];
    const float* b1  = (const float*)d_in[14];
    const float* Wm1 = (const float*)d_in[15];
    const float* bm1 = (const float*)d_in[16];
    const float* Wm2 = (const float*)d_in[17];
    const float* bm2 = (const float*)d_in[18];
    const float* Wm3 = (const float*)d_in[19];
    const float* bm3 = (const float*)d_in[20];

    int N = in_sizes[0] / 5;
    int E = in_sizes[1] / 2;
    const int* src = ei;
    const int* dst = ei + E;

    int NB = (N + 1023) / 1024;
    int EB = (E + 255) / 256;
    int GB = (N + 7) / 8;        // gather/pool blocks (8 nodes per block)

    k_zero<<<(N + 255) / 256, 256>>>(N);
    k_meanEA<<<512, 256>>>(ea, E);
    k_deg<<<EB, 256>>>(dst, E);
    k_scanA<<<NB, 1024>>>(N);
    k_scanB<<<1, 64>>>(NB);
    k_scanC<<<NB, 1024>>>(N);
    k_place<<<EB, 256>>>(src, dst, E);
    k_pre<<<1, 256>>>(W0, as0, ad0, We0, ae0, W1, as1, ad1, We1, ae1, (float)E);

    // layer 0
    k_node0<<<N, 256>>>(x, W0, N);
    k_edge<0><<<EB, 256>>>(src, dst, ea, E);
    k_gather<0><<<GB, 256>>>(b0, N);

    // layer 1
    k_node1<<<(N + 31) / 32, 256>>>(W1, N);
    k_edge<1><<<EB, 256>>>(src, dst, ea, E);
    k_gather<1><<<GB, 256>>>(b1, N);

    // pooling + MLP
    k_poolfin<<<64, 256>>>(GB);
    k_fin<<<1, 256>>>(N);
    k_dot<<<(N * 32 + 255) / 256, 256>>>(N);
    k_exp<<<(N + 255) / 256, 256>>>(N);
    k_attpool<<<(N + 63) / 64, 256>>>(N);
    k_mlp<<<1, 256>>>(Wm1, bm1, Wm2, bm2, Wm3, bm3, (float*)d_out);
}

// round 5
// speedup vs baseline: 1.5709x; 1.0961x over previous
#include <cuda_runtime.h>
#include <cuda_fp16.h>
#include <cuda_bf16.h>
#include <cfloat>

#define N_MAX 50000
#define E_MAX 800000
#define PB_MAX ((N_MAX + 7) / 8)
#define LRELU 0.2f
#define ENC_NEGINF 0x007FFFFFu

// ---------------- device scratch ----------------
__device__ __half g_hh[N_MAX * 256];   // message features, fp16 (gather-only consumer)
__device__ float g_x1[N_MAX * 256];    // layer outputs (fp32)
__device__ float g_als[N_MAX * 4];
__device__ float g_ald[N_MAX * 4];
__device__ float g_p[E_MAX * 4];       // permuted (CSR order): g_p[pos*4+h]
__device__ int   g_deg[N_MAX];
__device__ int   g_offs[N_MAX];
__device__ int   g_cursor[N_MAX];
__device__ int   g_srcPerm[E_MAX];     // src node id in CSR position order
__device__ int   g_epos[E_MAX];        // edge -> CSR position
__device__ int   g_bsum[64];
__device__ int   g_bsumScan[64];
__device__ float g_poolSum[PB_MAX * 256];
__device__ float g_poolMax[PB_MAX * 256];

__device__ float g_asEff0[5 * 4], g_adEff0[5 * 4], g_aeEff0[4 * 4], g_selfae0[4];
__device__ float g_asEff1[256 * 4], g_adEff1[256 * 4], g_aeEff1[4 * 4], g_selfae1[4];
__device__ float g_meanRaw[4];

__device__ float    g_meansum[256];
__device__ unsigned g_maxbits[256];
__device__ float    g_attsum[256];
__device__ float    g_s[N_MAX];
__device__ float    g_pn[N_MAX];
__device__ unsigned g_smaxbits;
__device__ float    g_Z;

// ---------------- helpers ----------------
__device__ __forceinline__ unsigned encf(float f) {
    unsigned b = __float_as_uint(f);
    return (b & 0x80000000u) ? ~b : (b | 0x80000000u);
}
__device__ __forceinline__ float decf(unsigned u) {
    return (u & 0x80000000u) ? __uint_as_float(u ^ 0x80000000u) : __uint_as_float(~u);
}
__device__ __forceinline__ float lrelu(float a) { return a > 0.f ? a : LRELU * a; }

__device__ __forceinline__ unsigned long long packf2(float lo, float hi) {
    unsigned long long r;
    unsigned a = __float_as_uint(lo), b = __float_as_uint(hi);
    asm("mov.b64 %0, {%1, %2};" : "=l"(r) : "r"(a), "r"(b));
    return r;
}
__device__ __forceinline__ float unpack_sum(unsigned long long v) {
    unsigned a, b;
    asm("mov.b64 {%0, %1}, %2;" : "=r"(a), "=r"(b) : "l"(v));
    return __uint_as_float(a) + __uint_as_float(b);
}
__device__ __forceinline__ void ffma2(unsigned long long& acc, unsigned long long a,
                                      unsigned long long b) {
    asm("fma.rn.f32x2 %0, %1, %2, %0;" : "+l"(acc) : "l"(a), "l"(b));
}

// accumulate 8 fp16 channels (one uint4) scaled by p into 8 fp32 accumulators
__device__ __forceinline__ void acc8(float& a0, float& a1, float& a2, float& a3,
                                     float& a4, float& a5, float& a6, float& a7,
                                     uint4 u, float p) {
    float2 f;
    f = __half22float2(*(const __half2*)&u.x); a0 += p * f.x; a1 += p * f.y;
    f = __half22float2(*(const __half2*)&u.y); a2 += p * f.x; a3 += p * f.y;
    f = __half22float2(*(const __half2*)&u.z); a4 += p * f.x; a5 += p * f.y;
    f = __half22float2(*(const __half2*)&u.w); a6 += p * f.x; a7 += p * f.y;
}

// ---------------- setup kernels ----------------
__global__ void k_zero(int N) {
    int i = blockIdx.x * blockDim.x + threadIdx.x;
    if (i < N) { g_deg[i] = 0; g_cursor[i] = 0; }
    if (i < 256) { g_meansum[i] = 0.f; g_attsum[i] = 0.f; g_maxbits[i] = ENC_NEGINF; }
    if (i < 4) g_meanRaw[i] = 0.f;
    if (i == 0) { g_Z = 0.f; g_smaxbits = ENC_NEGINF; }
}

__global__ void k_meanEA(const float* __restrict__ ea, int E) {
    __shared__ float sm[256][4];
    float a0 = 0, a1 = 0, a2 = 0, a3 = 0;
    int stride = gridDim.x * blockDim.x;
    for (int e = blockIdx.x * blockDim.x + threadIdx.x; e < E; e += stride) {
        float4 v = ((const float4*)ea)[e];
        a0 += v.x; a1 += v.y; a2 += v.z; a3 += v.w;
    }
    sm[threadIdx.x][0] = a0; sm[threadIdx.x][1] = a1;
    sm[threadIdx.x][2] = a2; sm[threadIdx.x][3] = a3;
    __syncthreads();
    for (int s = 128; s > 0; s >>= 1) {
        if (threadIdx.x < s) {
            sm[threadIdx.x][0] += sm[threadIdx.x + s][0];
            sm[threadIdx.x][1] += sm[threadIdx.x + s][1];
            sm[threadIdx.x][2] += sm[threadIdx.x + s][2];
            sm[threadIdx.x][3] += sm[threadIdx.x + s][3];
        }
        __syncthreads();
    }
    if (threadIdx.x < 4) atomicAdd(&g_meanRaw[threadIdx.x], sm[0][threadIdx.x]);
}

__global__ void k_deg(const int* __restrict__ dst, int E) {
    int e = blockIdx.x * blockDim.x + threadIdx.x;
    if (e < E) atomicAdd(&g_deg[dst[e]], 1);
}

__global__ void k_scanA(int N) {
    __shared__ int sm[1024];
    int i = blockIdx.x * 1024 + threadIdx.x;
    int v = (i < N) ? g_deg[i] : 0;
    sm[threadIdx.x] = v;
    __syncthreads();
    for (int d = 1; d < 1024; d <<= 1) {
        int t = (threadIdx.x >= d) ? sm[threadIdx.x - d] : 0;
        __syncthreads();
        sm[threadIdx.x] += t;
        __syncthreads();
    }
    if (i < N) g_offs[i] = sm[threadIdx.x] - v;
    if (threadIdx.x == 1023) g_bsum[blockIdx.x] = sm[1023];
}

__global__ void k_scanB(int NB) {
    __shared__ int sm[64];
    int t = threadIdx.x;
    int orig = (t < NB) ? g_bsum[t] : 0;
    sm[t] = orig;
    __syncthreads();
    for (int d = 1; d < 64; d <<= 1) {
        int v = (t >= d) ? sm[t - d] : 0;
        __syncthreads();
        sm[t] += v;
        __syncthreads();
    }
    g_bsumScan[t] = sm[t] - orig;
}

__global__ void k_scanC(int N) {
    int i = blockIdx.x * 1024 + threadIdx.x;
    if (i < N) g_offs[i] += g_bsumScan[blockIdx.x];
}

__global__ void k_place(const int* __restrict__ src, const int* __restrict__ dst, int E) {
    int e = blockIdx.x * blockDim.x + threadIdx.x;
    if (e < E) {
        int d = dst[e];
        int pos = g_offs[d] + atomicAdd(&g_cursor[d], 1);
        g_epos[e] = pos;
        g_srcPerm[pos] = src[e];
    }
}

__global__ void k_pre(const float* __restrict__ W0, const float* __restrict__ as0,
                      const float* __restrict__ ad0, const float* __restrict__ We0,
                      const float* __restrict__ ae0, const float* __restrict__ W1,
                      const float* __restrict__ as1, const float* __restrict__ ad1,
                      const float* __restrict__ We1, const float* __restrict__ ae1,
                      float Ef) {
    __shared__ float sm_mean[4];
    int tid = threadIdx.x;
    for (int idx = tid; idx < 20; idx += 256) {
        int k = idx >> 2, h = idx & 3;
        float s1 = 0, s2 = 0;
        for (int c = 0; c < 64; c++) {
            float w = W0[k * 256 + h * 64 + c];
            s1 += w * as0[h * 64 + c]; s2 += w * ad0[h * 64 + c];
        }
        g_asEff0[idx] = s1; g_adEff0[idx] = s2;
    }
    for (int idx = tid; idx < 16; idx += 256) {
        int k = idx >> 2, h = idx & 3;
        float s0 = 0, s1 = 0;
        for (int c = 0; c < 64; c++) {
            s0 += We0[k * 256 + h * 64 + c] * ae0[h * 64 + c];
            s1 += We1[k * 256 + h * 64 + c] * ae1[h * 64 + c];
        }
        g_aeEff0[idx] = s0; g_aeEff1[idx] = s1;
    }
    for (int idx = tid; idx < 1024; idx += 256) {
        int k = idx >> 2, h = idx & 3;
        float s1 = 0, s2 = 0;
        for (int c = 0; c < 64; c++) {
            float w = W1[k * 256 + h * 64 + c];
            s1 += w * as1[h * 64 + c]; s2 += w * ad1[h * 64 + c];
        }
        g_asEff1[idx] = s1; g_adEff1[idx] = s2;
    }
    __syncthreads();
    if (tid < 4) sm_mean[tid] = g_meanRaw[tid] / Ef;
    __syncthreads();
    if (tid < 4) {
        float s0 = 0, s1 = 0;
        for (int k = 0; k < 4; k++) {
            s0 += sm_mean[k] * g_aeEff0[k * 4 + tid];
            s1 += sm_mean[k] * g_aeEff1[k * 4 + tid];
        }
        g_selfae0[tid] = s0; g_selfae1[tid] = s1;
    }
}

// ---------------- layer 0 node transform (h stored fp16) ----------------
__global__ void k_node0(const float* __restrict__ x, const float* __restrict__ W0, int N) {
    int n = blockIdx.x;
    if (n >= N) return;
    int tid = threadIdx.x;
    float xk[5];
#pragma unroll
    for (int k = 0; k < 5; k++) xk[k] = x[n * 5 + k];
    float s = 0.f;
#pragma unroll
    for (int k = 0; k < 5; k++) s += xk[k] * W0[k * 256 + tid];
    g_hh[(size_t)n * 256 + tid] = __float2half_rn(s);
    if (tid < 8) {
        int which = tid >> 2, h = tid & 3;
        const float* eff = which ? g_adEff0 : g_asEff0;
        float a = 0.f;
#pragma unroll
        for (int k = 0; k < 5; k++) a += xk[k] * eff[k * 4 + h];
        (which ? g_ald : g_als)[n * 4 + h] = a;
    }
}

// ---------------- per-edge attention weights (written in CSR order) ----------------
template <int L>
__global__ void k_edge(const int* __restrict__ src, const int* __restrict__ dst,
                       const float* __restrict__ ea, int E) {
    int e = blockIdx.x * blockDim.x + threadIdx.x;
    if (e >= E) return;
    const float* aeEff = L ? g_aeEff1 : g_aeEff0;
    float4 v = ((const float4*)ea)[e];
    int s = src[e], d = dst[e];
    float4 as = ((const float4*)g_als)[s];
    float4 ad = ((const float4*)g_ald)[d];
    float4 p;
    float ale;
    ale = v.x * aeEff[0] + v.y * aeEff[4] + v.z * aeEff[8] + v.w * aeEff[12];
    p.x = __expf(lrelu(as.x + ad.x + ale));
    ale = v.x * aeEff[1] + v.y * aeEff[5] + v.z * aeEff[9] + v.w * aeEff[13];
    p.y = __expf(lrelu(as.y + ad.y + ale));
    ale = v.x * aeEff[2] + v.y * aeEff[6] + v.z * aeEff[10] + v.w * aeEff[14];
    p.z = __expf(lrelu(as.z + ad.z + ale));
    ale = v.x * aeEff[3] + v.y * aeEff[7] + v.z * aeEff[11] + v.w * aeEff[15];
    p.w = __expf(lrelu(as.w + ad.w + ale));
    ((float4*)g_p)[g_epos[e]] = p;
}

// ---------------- gather: one warp per node, all 4 heads, fp16 messages ----------------
// lane owns channels [lane*8, lane*8+8); head = lane>>3
template <int L>
__global__ __launch_bounds__(256) void k_gather(const float* __restrict__ b, int N) {
    int wib = threadIdx.x >> 5;
    int lane = threadIdx.x & 31;
    int n = blockIdx.x * 8 + wib;
    int hh = lane >> 3;
    bool active = (n < N);
    float o0 = 0, o1 = 0, o2 = 0, o3 = 0, o4 = 0, o5 = 0, o6 = 0, o7 = 0;
    if (active) {
        const float* selfae = L ? g_selfae1 : g_selfae0;
        float pself = __expf(lrelu(g_als[n * 4 + hh] + g_ald[n * 4 + hh] + selfae[hh]));
        float a0 = 0, a1 = 0, a2 = 0, a3 = 0, a4 = 0, a5 = 0, a6 = 0, a7 = 0;
        {
            uint4 u = ((const uint4*)(g_hh + (size_t)n * 256))[lane];
            acc8(a0, a1, a2, a3, a4, a5, a6, a7, u, pself);
        }
        float denom = pself;
        int base = g_offs[n], deg = g_deg[n];
        for (int i0 = 0; i0 < deg; i0 += 32) {
            int cnt = min(32, deg - i0);
            int sl = 0;
            if (lane < cnt) sl = g_srcPerm[base + i0 + lane];
            int j = 0;
            for (; j + 4 <= cnt; j += 4) {
                int s0 = __shfl_sync(0xFFFFFFFFu, sl, j);
                int s1 = __shfl_sync(0xFFFFFFFFu, sl, j + 1);
                int s2 = __shfl_sync(0xFFFFFFFFu, sl, j + 2);
                int s3 = __shfl_sync(0xFFFFFFFFu, sl, j + 3);
                size_t pb = (size_t)(base + i0 + j) * 4 + hh;
                float p0 = g_p[pb], p1 = g_p[pb + 4], p2 = g_p[pb + 8], p3 = g_p[pb + 12];
                uint4 u0 = ((const uint4*)(g_hh + (size_t)s0 * 256))[lane];
                uint4 u1 = ((const uint4*)(g_hh + (size_t)s1 * 256))[lane];
                uint4 u2 = ((const uint4*)(g_hh + (size_t)s2 * 256))[lane];
                uint4 u3 = ((const uint4*)(g_hh + (size_t)s3 * 256))[lane];
                acc8(a0, a1, a2, a3, a4, a5, a6, a7, u0, p0);
                acc8(a0, a1, a2, a3, a4, a5, a6, a7, u1, p1);
                acc8(a0, a1, a2, a3, a4, a5, a6, a7, u2, p2);
                acc8(a0, a1, a2, a3, a4, a5, a6, a7, u3, p3);
                denom += p0 + p1 + p2 + p3;
            }
            for (; j < cnt; j++) {
                int s0 = __shfl_sync(0xFFFFFFFFu, sl, j);
                float p0 = g_p[(size_t)(base + i0 + j) * 4 + hh];
                uint4 u0 = ((const uint4*)(g_hh + (size_t)s0 * 256))[lane];
                acc8(a0, a1, a2, a3, a4, a5, a6, a7, u0, p0);
                denom += p0;
            }
        }
        float inv = 1.f / (denom + 1e-16f);
        int c = lane * 8;
        o0 = a0 * inv + b[c + 0]; o1 = a1 * inv + b[c + 1];
        o2 = a2 * inv + b[c + 2]; o3 = a3 * inv + b[c + 3];
        o4 = a4 * inv + b[c + 4]; o5 = a5 * inv + b[c + 5];
        o6 = a6 * inv + b[c + 6]; o7 = a7 * inv + b[c + 7];
        if (L == 0) {
            o0 = fmaxf(o0, 0.f); o1 = fmaxf(o1, 0.f); o2 = fmaxf(o2, 0.f); o3 = fmaxf(o3, 0.f);
            o4 = fmaxf(o4, 0.f); o5 = fmaxf(o5, 0.f); o6 = fmaxf(o6, 0.f); o7 = fmaxf(o7, 0.f);
        }
        float* op = g_x1 + (size_t)n * 256 + c;
        ((float4*)op)[0] = make_float4(o0, o1, o2, o3);
        ((float4*)op)[1] = make_float4(o4, o5, o6, o7);
    }
    if (L == 1) {
        // fused mean/max pool partials
        __shared__ float tile[8 * 256];
        if (active) {
            float* tp = tile + wib * 256 + lane * 8;
            ((float4*)tp)[0] = make_float4(o0, o1, o2, o3);
            ((float4*)tp)[1] = make_float4(o4, o5, o6, o7);
        }
        __syncthreads();
        int c = threadIdx.x;
        int nb = min(8, N - blockIdx.x * 8);
        float s = 0.f, m = -FLT_MAX;
        for (int w = 0; w < nb; w++) {
            float v = tile[w * 256 + c];
            s += v;
            m = fmaxf(m, v);
        }
        g_poolSum[(size_t)blockIdx.x * 256 + c] = s;
        g_poolMax[(size_t)blockIdx.x * 256 + c] = m;
    }
}

// ---------------- layer 1 node transform: 32 nodes/block, packed f32x2 FMA ----------------
__global__ __launch_bounds__(256) void k_node1(const float* __restrict__ W1, int N) {
    __shared__ __align__(16) float xs[32 * 256];
    int tid = threadIdx.x;
    int n0 = blockIdx.x * 32;
    for (int j = 0; j < 32; j++) {
        int n = n0 + j;
        xs[j * 256 + tid] = (n < N) ? g_x1[(size_t)n * 256 + tid] : 0.f;
    }
    __syncthreads();
    unsigned long long acc[32];
#pragma unroll
    for (int j = 0; j < 32; j++) acc[j] = 0ull;
    for (int k = 0; k < 256; k += 4) {
        float wa = W1[(k + 0) * 256 + tid];
        float wb = W1[(k + 1) * 256 + tid];
        float wc = W1[(k + 2) * 256 + tid];
        float wd = W1[(k + 3) * 256 + tid];
        unsigned long long w01 = packf2(wa, wb);
        unsigned long long w23 = packf2(wc, wd);
#pragma unroll
        for (int j = 0; j < 32; j++) {
            ulonglong2 x2 = *(const ulonglong2*)&xs[j * 256 + k];
            ffma2(acc[j], x2.x, w01);
            ffma2(acc[j], x2.y, w23);
        }
    }
    for (int j = 0; j < 32; j++) {
        int n = n0 + j;
        if (n < N) g_hh[(size_t)n * 256 + tid] = __float2half_rn(unpack_sum(acc[j]));
    }
    // attention logits: 32 nodes x 4 heads x {src,dst} = 256 tasks
    {
        const float* eff = (tid & 128) ? g_adEff1 : g_asEff1;
        int t2 = tid & 127;
        int j = t2 >> 2, h = t2 & 3;
        float s = 0.f;
        for (int k = 0; k < 256; k += 4) {
            float4 xv = *(const float4*)&xs[j * 256 + k];
            s += xv.x * eff[(k + 0) * 4 + h] + xv.y * eff[(k + 1) * 4 + h] +
                 xv.z * eff[(k + 2) * 4 + h] + xv.w * eff[(k + 3) * 4 + h];
        }
        int n = n0 + j;
        if (n < N) ((tid & 128) ? g_ald : g_als)[n * 4 + h] = s;
    }
}

// ---------------- pooling finalize ----------------
__global__ void k_poolfin(int NB) {
    int c = threadIdx.x;
    float s = 0.f, m = -FLT_MAX;
    for (int i = blockIdx.x; i < NB; i += gridDim.x) {
        s += g_poolSum[(size_t)i * 256 + c];
        m = fmaxf(m, g_poolMax[(size_t)i * 256 + c]);
    }
    atomicAdd(&g_meansum[c], s);
    atomicMax(&g_maxbits[c], encf(m));
}

__global__ void k_fin(int N) {
    int c = threadIdx.x;
    g_meansum[c] /= (float)N;
}

__global__ void k_dot(int N) {
    int gw = (blockIdx.x * blockDim.x + threadIdx.x) >> 5;
    int lane = threadIdx.x & 31;
    if (gw >= N) return;
    float s = 0.f;
#pragma unroll
    for (int i = 0; i < 8; i++) {
        int c = lane + i * 32;
        s += g_x1[(size_t)gw * 256 + c] * g_meansum[c];
    }
#pragma unroll
    for (int o = 16; o > 0; o >>= 1) s += __shfl_down_sync(0xFFFFFFFFu, s, o);
    if (lane == 0) {
        g_s[gw] = s;
        atomicMax(&g_smaxbits, encf(s));
    }
}

__global__ void k_exp(int N) {
    __shared__ float sm[256];
    int i = blockIdx.x * blockDim.x + threadIdx.x;
    float smax = decf(g_smaxbits);
    float v = 0.f;
    if (i < N) {
        v = __expf(g_s[i] - smax);
        g_pn[i] = v;
    }
    sm[threadIdx.x] = v;
    __syncthreads();
    for (int s = 128; s > 0; s >>= 1) {
        if (threadIdx.x < s) sm[threadIdx.x] += sm[threadIdx.x + s];
        __syncthreads();
    }
    if (threadIdx.x == 0) atomicAdd(&g_Z, sm[0]);
}

__global__ void k_attpool(int N) {
    int c = threadIdx.x;
    int nb = blockIdx.x * 64;
    float s = 0.f;
    for (int j = 0; j < 64; j++) {
        int n = nb + j;
        if (n < N) s += g_x1[(size_t)n * 256 + c] * g_pn[n];
    }
    atomicAdd(&g_attsum[c], s);
}

__global__ void k_mlp(const float* __restrict__ Wm1, const float* __restrict__ bm1,
                      const float* __restrict__ Wm2, const float* __restrict__ bm2,
                      const float* __restrict__ Wm3, const float* __restrict__ bm3,
                      float* __restrict__ out) {
    __shared__ float comb[768], z1[128], z2[64];
    int tid = threadIdx.x;
    float Zinv = 1.f / g_Z;
    comb[tid] = g_meansum[tid];
    comb[256 + tid] = decf(g_maxbits[tid]);
    comb[512 + tid] = g_attsum[tid] * Zinv;
    __syncthreads();
    if (tid < 128) {
        float s = bm1[tid];
        for (int k = 0; k < 768; k++) s += comb[k] * Wm1[k * 128 + tid];
        z1[tid] = fmaxf(s, 0.f);
    }
    __syncthreads();
    if (tid < 64) {
        float s = bm2[tid];
        for (int k = 0; k < 128; k++) s += z1[k] * Wm2[k * 64 + tid];
        z2[tid] = fmaxf(s, 0.f);
    }
    __syncthreads();
    if (tid < 128) {
        float s = bm3[tid];
        for (int k = 0; k < 64; k++) s += z2[k] * Wm3[k * 128 + tid];
        out[tid] = s;
    }
}

// ---------------- launch ----------------
extern "C" void kernel_launch(void* const* d_in, const int* in_sizes, int n_in,
                              void* d_out, int out_size) {
    const float* x   = (const float*)d_in[0];
    const int*   ei  = (const int*)d_in[1];
    const float* ea  = (const float*)d_in[2];
    const float* W0  = (const float*)d_in[3];
    const float* as0 = (const float*)d_in[4];
    const float* ad0 = (const float*)d_in[5];
    const float* We0 = (const float*)d_in[6];
    const float* ae0 = (const float*)d_in[7];
    const float* b0  = (const float*)d_in[8];
    const float* W1  = (const float*)d_in[9];
    const float* as1 = (const float*)d_in[10];
    const float* ad1 = (const float*)d_in[11];
    const float* We1 = (const float*)d_in[12];
    const float* ae1 = (const float*)d_in[13];
    const float* b1  = (const float*)d_in[14];
    const float* Wm1 = (const float*)d_in[15];
    const float* bm1 = (const float*)d_in[16];
    const float* Wm2 = (const float*)d_in[17];
    const float* bm2 = (const float*)d_in[18];
    const float* Wm3 = (const float*)d_in[19];
    const float* bm3 = (const float*)d_in[20];

    int N = in_sizes[0] / 5;
    int E = in_sizes[1] / 2;
    const int* src = ei;
    const int* dst = ei + E;

    int NB = (N + 1023) / 1024;
    int EB = (E + 255) / 256;
    int GB = (N + 7) / 8;

    k_zero<<<(N + 255) / 256, 256>>>(N);
    k_meanEA<<<512, 256>>>(ea, E);
    k_deg<<<EB, 256>>>(dst, E);
    k_scanA<<<NB, 1024>>>(N);
    k_scanB<<<1, 64>>>(NB);
    k_scanC<<<NB, 1024>>>(N);
    k_place<<<EB, 256>>>(src, dst, E);
    k_pre<<<1, 256>>>(W0, as0, ad0, We0, ae0, W1, as1, ad1, We1, ae1, (float)E);

    // layer 0
    k_node0<<<N, 256>>>(x, W0, N);
    k_edge<0><<<EB, 256>>>(src, dst, ea, E);
    k_gather<0><<<GB, 256>>>(b0, N);

    // layer 1
    k_node1<<<(N + 31) / 32, 256>>>(W1, N);
    k_edge<1><<<EB, 256>>>(src, dst, ea, E);
    k_gather<1><<<GB, 256>>>(b1, N);

    // pooling + MLP
    k_poolfin<<<64, 256>>>(GB);
    k_fin<<<1, 256>>>(N);
    k_dot<<<(N * 32 + 255) / 256, 256>>>(N);
    k_exp<<<(N + 255) / 256, 256>>>(N);
    k_attpool<<<(N + 63) / 64, 256>>>(N);
    k_mlp<<<1, 256>>>(Wm1, bm1, Wm2, bm2, Wm3, bm3, (float*)d_out);
}

// round 7
// speedup vs baseline: 2.5255x; 1.6077x over previous
#include <cuda_runtime.h>
#include <cuda_fp16.h>
#include <cuda_bf16.h>
#include <cfloat>

#define N_MAX 50000
#define E_MAX 800000
#define PB_MAX ((N_MAX + 7) / 8)
#define LRELU 0.2f
#define ENC_NEGINF 0x007FFFFFu

// ---------------- device scratch ----------------
__device__ __half g_hh[N_MAX * 256];   // message features fp16 (gather consumer)
__device__ __half g_x1h[N_MAX * 256];  // layer-0 output fp16 (node1mma A operand)
__device__ __half g_W1h[256 * 256];    // W1 transposed (n-major), fp16
__device__ float g_x1[N_MAX * 256];    // final layer output (fp32, pooling consumers)
__device__ float g_als[N_MAX * 4];
__device__ float g_ald[N_MAX * 4];
__device__ float g_p[E_MAX * 4];       // permuted (CSR order)
__device__ int   g_deg[N_MAX];
__device__ int   g_offs[N_MAX];
__device__ int   g_cursor[N_MAX];
__device__ int   g_srcPerm[E_MAX];
__device__ int   g_epos[E_MAX];
__device__ int   g_bsum[64];
__device__ int   g_bsumScan[64];
__device__ float g_poolSum[PB_MAX * 256];
__device__ float g_poolMax[PB_MAX * 256];

__device__ float g_asEff0[5 * 4], g_adEff0[5 * 4], g_aeEff0[4 * 4], g_selfae0[4];
__device__ float g_aeEff1[4 * 4], g_selfae1[4];
__device__ float g_meanRaw[4];

__device__ float    g_meansum[256];
__device__ unsigned g_maxbits[256];
__device__ float    g_attsum[256];
__device__ float    g_s[N_MAX];
__device__ float    g_pn[N_MAX];
__device__ unsigned g_smaxbits;
__device__ float    g_Z;

// ---------------- helpers ----------------
__device__ __forceinline__ unsigned encf(float f) {
    unsigned b = __float_as_uint(f);
    return (b & 0x80000000u) ? ~b : (b | 0x80000000u);
}
__device__ __forceinline__ float decf(unsigned u) {
    return (u & 0x80000000u) ? __uint_as_float(u ^ 0x80000000u) : __uint_as_float(~u);
}
__device__ __forceinline__ float lrelu(float a) { return a > 0.f ? a : LRELU * a; }

__device__ __forceinline__ void acc8(float& a0, float& a1, float& a2, float& a3,
                                     float& a4, float& a5, float& a6, float& a7,
                                     uint4 u, float p) {
    float2 f;
    f = __half22float2(*(const __half2*)&u.x); a0 += p * f.x; a1 += p * f.y;
    f = __half22float2(*(const __half2*)&u.y); a2 += p * f.x; a3 += p * f.y;
    f = __half22float2(*(const __half2*)&u.z); a4 += p * f.x; a5 += p * f.y;
    f = __half22float2(*(const __half2*)&u.w); a6 += p * f.x; a7 += p * f.y;
}

__device__ __forceinline__ void mma16816(float& c0, float& c1, float& c2, float& c3,
                                         unsigned a0, unsigned a1, unsigned a2, unsigned a3,
                                         unsigned b0, unsigned b1) {
    asm volatile(
        "mma.sync.aligned.m16n8k16.row.col.f32.f16.f16.f32 "
        "{%0,%1,%2,%3}, {%4,%5,%6,%7}, {%8,%9}, {%0,%1,%2,%3};"
        : "+f"(c0), "+f"(c1), "+f"(c2), "+f"(c3)
        : "r"(a0), "r"(a1), "r"(a2), "r"(a3), "r"(b0), "r"(b1));
}

// ---------------- setup kernels ----------------
__global__ void k_zero(int N) {
    int i = blockIdx.x * blockDim.x + threadIdx.x;
    if (i < N) { g_deg[i] = 0; g_cursor[i] = 0; }
    if (i < 256) { g_meansum[i] = 0.f; g_attsum[i] = 0.f; g_maxbits[i] = ENC_NEGINF; }
    if (i < 4) g_meanRaw[i] = 0.f;
    if (i == 0) { g_Z = 0.f; g_smaxbits = ENC_NEGINF; }
}

__global__ void k_meanEA(const float* __restrict__ ea, int E) {
    __shared__ float sm[256][4];
    float a0 = 0, a1 = 0, a2 = 0, a3 = 0;
    int stride = gridDim.x * blockDim.x;
    for (int e = blockIdx.x * blockDim.x + threadIdx.x; e < E; e += stride) {
        float4 v = ((const float4*)ea)[e];
        a0 += v.x; a1 += v.y; a2 += v.z; a3 += v.w;
    }
    sm[threadIdx.x][0] = a0; sm[threadIdx.x][1] = a1;
    sm[threadIdx.x][2] = a2; sm[threadIdx.x][3] = a3;
    __syncthreads();
    for (int s = 128; s > 0; s >>= 1) {
        if (threadIdx.x < s) {
            sm[threadIdx.x][0] += sm[threadIdx.x + s][0];
            sm[threadIdx.x][1] += sm[threadIdx.x + s][1];
            sm[threadIdx.x][2] += sm[threadIdx.x + s][2];
            sm[threadIdx.x][3] += sm[threadIdx.x + s][3];
        }
        __syncthreads();
    }
    if (threadIdx.x < 4) atomicAdd(&g_meanRaw[threadIdx.x], sm[0][threadIdx.x]);
}

__global__ void k_deg(const int* __restrict__ dst, int E) {
    int e = blockIdx.x * blockDim.x + threadIdx.x;
    if (e < E) atomicAdd(&g_deg[dst[e]], 1);
}

__global__ void k_scanA(int N) {
    __shared__ int sm[1024];
    int i = blockIdx.x * 1024 + threadIdx.x;
    int v = (i < N) ? g_deg[i] : 0;
    sm[threadIdx.x] = v;
    __syncthreads();
    for (int d = 1; d < 1024; d <<= 1) {
        int t = (threadIdx.x >= d) ? sm[threadIdx.x - d] : 0;
        __syncthreads();
        sm[threadIdx.x] += t;
        __syncthreads();
    }
    if (i < N) g_offs[i] = sm[threadIdx.x] - v;
    if (threadIdx.x == 1023) g_bsum[blockIdx.x] = sm[1023];
}

__global__ void k_scanB(int NB) {
    __shared__ int sm[64];
    int t = threadIdx.x;
    int orig = (t < NB) ? g_bsum[t] : 0;
    sm[t] = orig;
    __syncthreads();
    for (int d = 1; d < 64; d <<= 1) {
        int v = (t >= d) ? sm[t - d] : 0;
        __syncthreads();
        sm[t] += v;
        __syncthreads();
    }
    g_bsumScan[t] = sm[t] - orig;
}

__global__ void k_scanC(int N) {
    int i = blockIdx.x * 1024 + threadIdx.x;
    if (i < N) g_offs[i] += g_bsumScan[blockIdx.x];
}

__global__ void k_place(const int* __restrict__ src, const int* __restrict__ dst, int E) {
    int e = blockIdx.x * blockDim.x + threadIdx.x;
    if (e < E) {
        int d = dst[e];
        int pos = g_offs[d] + atomicAdd(&g_cursor[d], 1);
        g_epos[e] = pos;
        g_srcPerm[pos] = src[e];
    }
}

__global__ void k_w1h(const float* __restrict__ W1) {
    int idx = blockIdx.x * 256 + threadIdx.x;   // 65536
    int k = idx >> 8, n = idx & 255;
    g_W1h[n * 256 + k] = __float2half_rn(W1[k * 256 + n]);
}

__global__ void k_pre(const float* __restrict__ W0, const float* __restrict__ as0,
                      const float* __restrict__ ad0, const float* __restrict__ We0,
                      const float* __restrict__ ae0,
                      const float* __restrict__ We1, const float* __restrict__ ae1,
                      float Ef) {
    __shared__ float sm_mean[4];
    int tid = threadIdx.x;
    for (int idx = tid; idx < 20; idx += 256) {
        int k = idx >> 2, h = idx & 3;
        float s1 = 0, s2 = 0;
        for (int c = 0; c < 64; c++) {
            float w = W0[k * 256 + h * 64 + c];
            s1 += w * as0[h * 64 + c]; s2 += w * ad0[h * 64 + c];
        }
        g_asEff0[idx] = s1; g_adEff0[idx] = s2;
    }
    for (int idx = tid; idx < 16; idx += 256) {
        int k = idx >> 2, h = idx & 3;
        float s0 = 0, s1 = 0;
        for (int c = 0; c < 64; c++) {
            s0 += We0[k * 256 + h * 64 + c] * ae0[h * 64 + c];
            s1 += We1[k * 256 + h * 64 + c] * ae1[h * 64 + c];
        }
        g_aeEff0[idx] = s0; g_aeEff1[idx] = s1;
    }
    __syncthreads();
    if (tid < 4) sm_mean[tid] = g_meanRaw[tid] / Ef;
    __syncthreads();
    if (tid < 4) {
        float s0 = 0, s1 = 0;
        for (int k = 0; k < 4; k++) {
            s0 += sm_mean[k] * g_aeEff0[k * 4 + tid];
            s1 += sm_mean[k] * g_aeEff1[k * 4 + tid];
        }
        g_selfae0[tid] = s0; g_selfae1[tid] = s1;
    }
}

// ---------------- layer 0 node transform (h fp16) ----------------
__global__ void k_node0(const float* __restrict__ x, const float* __restrict__ W0, int N) {
    int n = blockIdx.x;
    if (n >= N) return;
    int tid = threadIdx.x;
    float xk[5];
#pragma unroll
    for (int k = 0; k < 5; k++) xk[k] = x[n * 5 + k];
    float s = 0.f;
#pragma unroll
    for (int k = 0; k < 5; k++) s += xk[k] * W0[k * 256 + tid];
    g_hh[(size_t)n * 256 + tid] = __float2half_rn(s);
    if (tid < 8) {
        int which = tid >> 2, h = tid & 3;
        const float* eff = which ? g_adEff0 : g_asEff0;
        float a = 0.f;
#pragma unroll
        for (int k = 0; k < 5; k++) a += xk[k] * eff[k * 4 + h];
        (which ? g_ald : g_als)[n * 4 + h] = a;
    }
}

// ---------------- per-edge attention weights (written in CSR order) ----------------
template <int L>
__global__ void k_edge(const int* __restrict__ src, const int* __restrict__ dst,
                       const float* __restrict__ ea, int E) {
    int e = blockIdx.x * blockDim.x + threadIdx.x;
    if (e >= E) return;
    const float* aeEff = L ? g_aeEff1 : g_aeEff0;
    float4 v = ((const float4*)ea)[e];
    int s = src[e], d = dst[e];
    float4 as = ((const float4*)g_als)[s];
    float4 ad = ((const float4*)g_ald)[d];
    float4 p;
    float ale;
    ale = v.x * aeEff[0] + v.y * aeEff[4] + v.z * aeEff[8] + v.w * aeEff[12];
    p.x = __expf(lrelu(as.x + ad.x + ale));
    ale = v.x * aeEff[1] + v.y * aeEff[5] + v.z * aeEff[9] + v.w * aeEff[13];
    p.y = __expf(lrelu(as.y + ad.y + ale));
    ale = v.x * aeEff[2] + v.y * aeEff[6] + v.z * aeEff[10] + v.w * aeEff[14];
    p.z = __expf(lrelu(as.z + ad.z + ale));
    ale = v.x * aeEff[3] + v.y * aeEff[7] + v.z * aeEff[11] + v.w * aeEff[15];
    p.w = __expf(lrelu(as.w + ad.w + ale));
    ((float4*)g_p)[g_epos[e]] = p;
}

// ---------------- gather: warp per node, fp16 messages, 8-edge unroll ----------------
template <int L>
__global__ __launch_bounds__(256) void k_gather(const float* __restrict__ b, int N) {
    int wib = threadIdx.x >> 5;
    int lane = threadIdx.x & 31;
    int n = blockIdx.x * 8 + wib;
    int hh = lane >> 3;
    bool active = (n < N);
    float o0 = 0, o1 = 0, o2 = 0, o3 = 0, o4 = 0, o5 = 0, o6 = 0, o7 = 0;
    if (active) {
        const float* selfae = L ? g_selfae1 : g_selfae0;
        float pself = __expf(lrelu(g_als[n * 4 + hh] + g_ald[n * 4 + hh] + selfae[hh]));
        float a0 = 0, a1 = 0, a2 = 0, a3 = 0, a4 = 0, a5 = 0, a6 = 0, a7 = 0;
        {
            uint4 u = ((const uint4*)(g_hh + (size_t)n * 256))[lane];
            acc8(a0, a1, a2, a3, a4, a5, a6, a7, u, pself);
        }
        float denom = pself;
        int base = g_offs[n], deg = g_deg[n];
        for (int i0 = 0; i0 < deg; i0 += 32) {
            int cnt = min(32, deg - i0);
            int sl = 0;
            if (lane < cnt) sl = g_srcPerm[base + i0 + lane];
            int j = 0;
            for (; j + 8 <= cnt; j += 8) {
                int s0 = __shfl_sync(0xFFFFFFFFu, sl, j);
                int s1 = __shfl_sync(0xFFFFFFFFu, sl, j + 1);
                int s2 = __shfl_sync(0xFFFFFFFFu, sl, j + 2);
                int s3 = __shfl_sync(0xFFFFFFFFu, sl, j + 3);
                int s4 = __shfl_sync(0xFFFFFFFFu, sl, j + 4);
                int s5 = __shfl_sync(0xFFFFFFFFu, sl, j + 5);
                int s6 = __shfl_sync(0xFFFFFFFFu, sl, j + 6);
                int s7 = __shfl_sync(0xFFFFFFFFu, sl, j + 7);
                size_t pb = (size_t)(base + i0 + j) * 4 + hh;
                float p0 = g_p[pb], p1 = g_p[pb + 4], p2 = g_p[pb + 8], p3 = g_p[pb + 12];
                float p4 = g_p[pb + 16], p5 = g_p[pb + 20], p6 = g_p[pb + 24], p7 = g_p[pb + 28];
                uint4 u0 = ((const uint4*)(g_hh + (size_t)s0 * 256))[lane];
                uint4 u1 = ((const uint4*)(g_hh + (size_t)s1 * 256))[lane];
                uint4 u2 = ((const uint4*)(g_hh + (size_t)s2 * 256))[lane];
                uint4 u3 = ((const uint4*)(g_hh + (size_t)s3 * 256))[lane];
                uint4 u4 = ((const uint4*)(g_hh + (size_t)s4 * 256))[lane];
                uint4 u5 = ((const uint4*)(g_hh + (size_t)s5 * 256))[lane];
                uint4 u6 = ((const uint4*)(g_hh + (size_t)s6 * 256))[lane];
                uint4 u7 = ((const uint4*)(g_hh + (size_t)s7 * 256))[lane];
                acc8(a0, a1, a2, a3, a4, a5, a6, a7, u0, p0);
                acc8(a0, a1, a2, a3, a4, a5, a6, a7, u1, p1);
                acc8(a0, a1, a2, a3, a4, a5, a6, a7, u2, p2);
                acc8(a0, a1, a2, a3, a4, a5, a6, a7, u3, p3);
                acc8(a0, a1, a2, a3, a4, a5, a6, a7, u4, p4);
                acc8(a0, a1, a2, a3, a4, a5, a6, a7, u5, p5);
                acc8(a0, a1, a2, a3, a4, a5, a6, a7, u6, p6);
                acc8(a0, a1, a2, a3, a4, a5, a6, a7, u7, p7);
                denom += p0 + p1 + p2 + p3 + p4 + p5 + p6 + p7;
            }
            for (; j < cnt; j++) {
                int s0 = __shfl_sync(0xFFFFFFFFu, sl, j);
                float p0 = g_p[(size_t)(base + i0 + j) * 4 + hh];
                uint4 u0 = ((const uint4*)(g_hh + (size_t)s0 * 256))[lane];
                acc8(a0, a1, a2, a3, a4, a5, a6, a7, u0, p0);
                denom += p0;
            }
        }
        float inv = 1.f / (denom + 1e-16f);
        int c = lane * 8;
        o0 = a0 * inv + b[c + 0]; o1 = a1 * inv + b[c + 1];
        o2 = a2 * inv + b[c + 2]; o3 = a3 * inv + b[c + 3];
        o4 = a4 * inv + b[c + 4]; o5 = a5 * inv + b[c + 5];
        o6 = a6 * inv + b[c + 6]; o7 = a7 * inv + b[c + 7];
        if (L == 0) {
            o0 = fmaxf(o0, 0.f); o1 = fmaxf(o1, 0.f); o2 = fmaxf(o2, 0.f); o3 = fmaxf(o3, 0.f);
            o4 = fmaxf(o4, 0.f); o5 = fmaxf(o5, 0.f); o6 = fmaxf(o6, 0.f); o7 = fmaxf(o7, 0.f);
            // layer-0 output consumed only by node1mma -> store fp16
            __half2 q0 = __floats2half2_rn(o0, o1), q1 = __floats2half2_rn(o2, o3);
            __half2 q2 = __floats2half2_rn(o4, o5), q3 = __floats2half2_rn(o6, o7);
            uint4 pk;
            pk.x = *(unsigned*)&q0; pk.y = *(unsigned*)&q1;
            pk.z = *(unsigned*)&q2; pk.w = *(unsigned*)&q3;
            ((uint4*)(g_x1h + (size_t)n * 256))[lane] = pk;
        } else {
            float* op = g_x1 + (size_t)n * 256 + c;
            ((float4*)op)[0] = make_float4(o0, o1, o2, o3);
            ((float4*)op)[1] = make_float4(o4, o5, o6, o7);
        }
    }
    if (L == 1) {
        __shared__ float tile[8 * 256];
        if (active) {
            float* tp = tile + wib * 256 + lane * 8;
            ((float4*)tp)[0] = make_float4(o0, o1, o2, o3);
            ((float4*)tp)[1] = make_float4(o4, o5, o6, o7);
        }
        __syncthreads();
        int c = threadIdx.x;
        int nb = min(8, N - blockIdx.x * 8);
        float s = 0.f, m = -FLT_MAX;
        for (int w = 0; w < nb; w++) {
            float v = tile[w * 256 + c];
            s += v;
            m = fmaxf(m, v);
        }
        g_poolSum[(size_t)blockIdx.x * 256 + c] = s;
        g_poolMax[(size_t)blockIdx.x * 256 + c] = m;
    }
}

// ---------------- layer 1 node transform: tensor-core GEMM ----------------
// h1[64 x 256] = x1h[64 x 256] @ W1  (A smem fp16, B = g_W1h n-major from global)
#define A_STRIDE 264  // halves: 512B row + 16B pad -> conflict-free ldmatrix
__global__ __launch_bounds__(256) void k_node1mma(int N) {
    __shared__ __align__(16) __half As[64 * A_STRIDE];
    int tid = threadIdx.x;
    int warp = tid >> 5, lane = tid & 31;
    int m0 = blockIdx.x * 64;
    // load A tile: 64 rows x 32 uint4
    for (int idx = tid; idx < 64 * 32; idx += 256) {
        int r = idx >> 5, c = idx & 31;
        int nrow = m0 + r;
        uint4 v = make_uint4(0, 0, 0, 0);
        if (nrow < N) v = ((const uint4*)(g_x1h + (size_t)nrow * 256))[c];
        *(uint4*)&As[r * A_STRIDE + c * 8] = v;
    }
    __syncthreads();

    float acc[4][4][4];
#pragma unroll
    for (int mt = 0; mt < 4; mt++)
#pragma unroll
        for (int nt = 0; nt < 4; nt++)
#pragma unroll
            for (int r = 0; r < 4; r++) acc[mt][nt][r] = 0.f;

    int nbase = warp * 32;
    for (int k0 = 0; k0 < 256; k0 += 16) {
        unsigned aR[4][4];
        int arow = lane & 15;
        int acol = k0 + ((lane >> 4) << 3);
#pragma unroll
        for (int mt = 0; mt < 4; mt++) {
            unsigned saddr =
                (unsigned)__cvta_generic_to_shared(&As[(mt * 16 + arow) * A_STRIDE + acol]);
            asm volatile("ldmatrix.sync.aligned.m8n8.x4.shared.b16 {%0,%1,%2,%3}, [%4];"
                         : "=r"(aR[mt][0]), "=r"(aR[mt][1]), "=r"(aR[mt][2]), "=r"(aR[mt][3])
                         : "r"(saddr));
        }
#pragma unroll
        for (int nt = 0; nt < 4; nt++) {
            const __half* bp =
                g_W1h + (size_t)(nbase + nt * 8 + (lane >> 2)) * 256 + k0 + ((lane & 3) << 1);
            unsigned b0 = *(const unsigned*)bp;
            unsigned b1 = *(const unsigned*)(bp + 8);
#pragma unroll
            for (int mt = 0; mt < 4; mt++)
                mma16816(acc[mt][nt][0], acc[mt][nt][1], acc[mt][nt][2], acc[mt][nt][3],
                         aR[mt][0], aR[mt][1], aR[mt][2], aR[mt][3], b0, b1);
        }
    }
    // epilogue: fp32 acc -> fp16 g_hh
#pragma unroll
    for (int mt = 0; mt < 4; mt++) {
#pragma unroll
        for (int nt = 0; nt < 4; nt++) {
            int r0 = m0 + mt * 16 + (lane >> 2);
            int cc = nbase + nt * 8 + ((lane & 3) << 1);
            if (r0 < N) {
                __half2 v = __floats2half2_rn(acc[mt][nt][0], acc[mt][nt][1]);
                *(__half2*)&g_hh[(size_t)r0 * 256 + cc] = v;
            }
            int r1 = r0 + 8;
            if (r1 < N) {
                __half2 v = __floats2half2_rn(acc[mt][nt][2], acc[mt][nt][3]);
                *(__half2*)&g_hh[(size_t)r1 * 256 + cc] = v;
            }
        }
    }
}

// ---------------- layer-1 attention logits from h1 ----------------
__global__ __launch_bounds__(256) void k_logits1(const float* __restrict__ as1,
                                                 const float* __restrict__ ad1, int N) {
    __shared__ float sa[256], sd[256];
    sa[threadIdx.x] = as1[threadIdx.x];
    sd[threadIdx.x] = ad1[threadIdx.x];
    __syncthreads();
    int wib = threadIdx.x >> 5, lane = threadIdx.x & 31;
    int n = blockIdx.x * 8 + wib;
    if (n >= N) return;
    int hh = lane >> 3;
    int c = lane * 8;
    uint4 u = ((const uint4*)(g_hh + (size_t)n * 256))[lane];
    float2 f0 = __half22float2(*(const __half2*)&u.x);
    float2 f1 = __half22float2(*(const __half2*)&u.y);
    float2 f2 = __half22float2(*(const __half2*)&u.z);
    float2 f3 = __half22float2(*(const __half2*)&u.w);
    float s = f0.x * sa[c] + f0.y * sa[c + 1] + f1.x * sa[c + 2] + f1.y * sa[c + 3] +
              f2.x * sa[c + 4] + f2.y * sa[c + 5] + f3.x * sa[c + 6] + f3.y * sa[c + 7];
    float d = f0.x * sd[c] + f0.y * sd[c + 1] + f1.x * sd[c + 2] + f1.y * sd[c + 3] +
              f2.x * sd[c + 4] + f2.y * sd[c + 5] + f3.x * sd[c + 6] + f3.y * sd[c + 7];
#pragma unroll
    for (int o = 4; o > 0; o >>= 1) {
        s += __shfl_xor_sync(0xFFFFFFFFu, s, o);
        d += __shfl_xor_sync(0xFFFFFFFFu, d, o);
    }
    if ((lane & 7) == 0) {
        g_als[n * 4 + hh] = s;
        g_ald[n * 4 + hh] = d;
    }
}

// ---------------- pooling finalize + tail ----------------
__global__ void k_poolfin(int NB) {
    int c = threadIdx.x;
    float s = 0.f, m = -FLT_MAX;
    for (int i = blockIdx.x; i < NB; i += gridDim.x) {
        s += g_poolSum[(size_t)i * 256 + c];
        m = fmaxf(m, g_poolMax[(size_t)i * 256 + c]);
    }
    atomicAdd(&g_meansum[c], s);
    atomicMax(&g_maxbits[c], encf(m));
}

__global__ void k_fin(int N) {
    int c = threadIdx.x;
    g_meansum[c] /= (float)N;
}

__global__ void k_dot(int N) {
    int gw = (blockIdx.x * blockDim.x + threadIdx.x) >> 5;
    int lane = threadIdx.x & 31;
    if (gw >= N) return;
    float s = 0.f;
#pragma unroll
    for (int i = 0; i < 8; i++) {
        int c = lane + i * 32;
        s += g_x1[(size_t)gw * 256 + c] * g_meansum[c];
    }
#pragma unroll
    for (int o = 16; o > 0; o >>= 1) s += __shfl_down_sync(0xFFFFFFFFu, s, o);
    if (lane == 0) {
        g_s[gw] = s;
        atomicMax(&g_smaxbits, encf(s));
    }
}

__global__ void k_exp(int N) {
    __shared__ float sm[256];
    int i = blockIdx.x * blockDim.x + threadIdx.x;
    float smax = decf(g_smaxbits);
    float v = 0.f;
    if (i < N) {
        v = __expf(g_s[i] - smax);
        g_pn[i] = v;
    }
    sm[threadIdx.x] = v;
    __syncthreads();
    for (int s = 128; s > 0; s >>= 1) {
        if (threadIdx.x < s) sm[threadIdx.x] += sm[threadIdx.x + s];
        __syncthreads();
    }
    if (threadIdx.x == 0) atomicAdd(&g_Z, sm[0]);
}

__global__ void k_attpool(int N) {
    int c = threadIdx.x;
    int nb = blockIdx.x * 64;
    float s = 0.f;
    for (int j = 0; j < 64; j++) {
        int n = nb + j;
        if (n < N) s += g_x1[(size_t)n * 256 + c] * g_pn[n];
    }
    atomicAdd(&g_attsum[c], s);
}

__global__ void k_mlp(const float* __restrict__ Wm1, const float* __restrict__ bm1,
                      const float* __restrict__ Wm2, const float* __restrict__ bm2,
                      const float* __restrict__ Wm3, const float* __restrict__ bm3,
                      float* __restrict__ out) {
    __shared__ float comb[768], z1[128], z2[64];
    int tid = threadIdx.x;
    float Zinv = 1.f / g_Z;
    comb[tid] = g_meansum[tid];
    comb[256 + tid] = decf(g_maxbits[tid]);
    comb[512 + tid] = g_attsum[tid] * Zinv;
    __syncthreads();
    if (tid < 128) {
        float s = bm1[tid];
        for (int k = 0; k < 768; k++) s += comb[k] * Wm1[k * 128 + tid];
        z1[tid] = fmaxf(s, 0.f);
    }
    __syncthreads();
    if (tid < 64) {
        float s = bm2[tid];
        for (int k = 0; k < 128; k++) s += z1[k] * Wm2[k * 64 + tid];
        z2[tid] = fmaxf(s, 0.f);
    }
    __syncthreads();
    if (tid < 128) {
        float s = bm3[tid];
        for (int k = 0; k < 64; k++) s += z2[k] * Wm3[k * 128 + tid];
        out[tid] = s;
    }
}

// ---------------- launch ----------------
extern "C" void kernel_launch(void* const* d_in, const int* in_sizes, int n_in,
                              void* d_out, int out_size) {
    const float* x   = (const float*)d_in[0];
    const int*   ei  = (const int*)d_in[1];
    const float* ea  = (const float*)d_in[2];
    const float* W0  = (const float*)d_in[3];
    const float* as0 = (const float*)d_in[4];
    const float* ad0 = (const float*)d_in[5];
    const float* We0 = (const float*)d_in[6];
    const float* ae0 = (const float*)d_in[7];
    const float* b0  = (const float*)d_in[8];
    const float* W1  = (const float*)d_in[9];
    const float* as1 = (const float*)d_in[10];
    const float* ad1 = (const float*)d_in[11];
    const float* We1 = (const float*)d_in[12];
    const float* ae1 = (const float*)d_in[13];
    const float* b1  = (const float*)d_in[14];
    const float* Wm1 = (const float*)d_in[15];
    const float* bm1 = (const float*)d_in[16];
    const float* Wm2 = (const float*)d_in[17];
    const float* bm2 = (const float*)d_in[18];
    const float* Wm3 = (const float*)d_in[19];
    const float* bm3 = (const float*)d_in[20];

    int N = in_sizes[0] / 5;
    int E = in_sizes[1] / 2;
    const int* src = ei;
    const int* dst = ei + E;

    int NB = (N + 1023) / 1024;
    int EB = (E + 255) / 256;
    int GB = (N + 7) / 8;

    k_zero<<<(N + 255) / 256, 256>>>(N);
    k_meanEA<<<512, 256>>>(ea, E);
    k_deg<<<EB, 256>>>(dst, E);
    k_scanA<<<NB, 1024>>>(N);
    k_scanB<<<1, 64>>>(NB);
    k_scanC<<<NB, 1024>>>(N);
    k_place<<<EB, 256>>>(src, dst, E);
    k_pre<<<1, 256>>>(W0, as0, ad0, We0, ae0, We1, ae1, (float)E);
    k_w1h<<<256, 256>>>(W1);

    // layer 0
    k_node0<<<N, 256>>>(x, W0, N);
    k_edge<0><<<EB, 256>>>(src, dst, ea, E);
    k_gather<0><<<GB, 256>>>(b0, N);

    // layer 1
    k_node1mma<<<(N + 63) / 64, 256>>>(N);
    k_logits1<<<GB, 256>>>(as1, ad1, N);
    k_edge<1><<<EB, 256>>>(src, dst, ea, E);
    k_gather<1><<<GB, 256>>>(b1, N);

    // pooling + MLP
    k_poolfin<<<64, 256>>>(GB);
    k_fin<<<1, 256>>>(N);
    k_dot<<<(N * 32 + 255) / 256, 256>>>(N);
    k_exp<<<(N + 255) / 256, 256>>>(N);
    k_attpool<<<(N + 63) / 64, 256>>>(N);
    k_mlp<<<1, 256>>>(Wm1, bm1, Wm2, bm2, Wm3, bm3, (float*)d_out);
}